// round 1
// baseline (speedup 1.0000x reference)
#include <cuda_runtime.h>
#include <cstdint>

#define BB 4
#define LL 4096
#define DD 1024

// ---------------- scratch (static device globals; no allocation) ----------------
__device__ float g_prob[BB*LL];
__device__ float g_decay[BB*LL];
__device__ int   g_src[BB*LL];
__device__ int   g_cidx[BB*LL];
__device__ int   g_counts[BB];
__device__ float g_ema[(size_t)BB*LL*DD];   // 64 MB

// ---------------- K1: fused router GEMM -> prob ----------------
#define BM 128
#define BN 128
#define BKK 16
#define AST 132   // padded shared stride

union F2U { unsigned long long u; float2 f; };

__device__ __forceinline__ unsigned long long dup2(float a){
    unsigned long long r;
    asm("mov.b64 %0, {%1, %1};" : "=l"(r) : "r"(__float_as_uint(a)));
    return r;
}
__device__ __forceinline__ void ffma2(unsigned long long& d, unsigned long long a, unsigned long long b){
    asm("fma.rn.f32x2 %0, %1, %2, %0;" : "+l"(d) : "l"(a), "l"(b));
}

__global__ __launch_bounds__(256, 1)
void k_router(const float* __restrict__ hid, const float* __restrict__ wq, const float* __restrict__ wk)
{
    __shared__ float sm[3*BKK*AST];
    float* As  = sm;
    float* Bqs = sm + BKK*AST;
    float* Bks = sm + 2*BKK*AST;

    const int b   = blockIdx.y;
    const int tt0 = blockIdx.x * BM;
    const float* hb = hid + (size_t)b*LL*DD;

    const int tid  = threadIdx.x;
    const int tx   = tid & 15;
    const int ty   = tid >> 4;
    const int row0 = ty * 8;
    const int e0l  = tx * 8;

    float qq[8], kk[8], qk[8];
#pragma unroll
    for (int i=0;i<8;i++){ qq[i]=0.f; kk[i]=0.f; qk[i]=0.f; }

    for (int et = 0; et < DD/BN; ++et) {
        unsigned long long qa[8][4], ka[8][4];
#pragma unroll
        for (int i=0;i<8;i++)
#pragma unroll
            for (int j=0;j<4;j++){ qa[i][j]=0ull; ka[i][j]=0ull; }

        const float* wqe = wq + (size_t)(et*BN)*DD;
        const float* wke = wk + (size_t)(et*BN)*DD;

        for (int kc = 0; kc < DD; kc += BKK) {
            __syncthreads();
            // A tile: rows tt0..tt0+128 (129 rows) x 16 k, stored transposed As[k][row]
            for (int v = tid; v < 129*4; v += 256) {
                int row = v >> 2;
                int k4  = (v & 3) << 2;
                float4 x = make_float4(0.f,0.f,0.f,0.f);
                int t = tt0 + row;
                if (t < LL) x = *(const float4*)(hb + (size_t)t*DD + kc + k4);
                As[(k4+0)*AST + row] = x.x;
                As[(k4+1)*AST + row] = x.y;
                As[(k4+2)*AST + row] = x.z;
                As[(k4+3)*AST + row] = x.w;
            }
            // Wq / Wk tiles: 128 e-rows x 16 k, stored transposed B[k][e]
            for (int v = tid; v < 128*4; v += 256) {
                int e  = v >> 2;
                int k4 = (v & 3) << 2;
                float4 xq = *(const float4*)(wqe + (size_t)e*DD + kc + k4);
                float4 xk = *(const float4*)(wke + (size_t)e*DD + kc + k4);
                Bqs[(k4+0)*AST + e] = xq.x;
                Bqs[(k4+1)*AST + e] = xq.y;
                Bqs[(k4+2)*AST + e] = xq.z;
                Bqs[(k4+3)*AST + e] = xq.w;
                Bks[(k4+0)*AST + e] = xk.x;
                Bks[(k4+1)*AST + e] = xk.y;
                Bks[(k4+2)*AST + e] = xk.z;
                Bks[(k4+3)*AST + e] = xk.w;
            }
            __syncthreads();

#pragma unroll
            for (int k = 0; k < BKK; ++k) {
                const float* arow = &As[k*AST];
                float4 av0 = *(const float4*)(arow + row0);
                float4 av1 = *(const float4*)(arow + row0 + 4);
                float a8   = arow[row0 + 8];
                float a[9] = {av0.x,av0.y,av0.z,av0.w,av1.x,av1.y,av1.z,av1.w,a8};

                ulonglong2 bq0 = *(const ulonglong2*)(&Bqs[k*AST + e0l]);
                ulonglong2 bq1 = *(const ulonglong2*)(&Bqs[k*AST + e0l + 4]);
                ulonglong2 bk0 = *(const ulonglong2*)(&Bks[k*AST + e0l]);
                ulonglong2 bk1 = *(const ulonglong2*)(&Bks[k*AST + e0l + 4]);
#pragma unroll
                for (int i=0;i<8;i++){
                    unsigned long long adq = dup2(a[i]);
                    ffma2(qa[i][0], adq, bq0.x);
                    ffma2(qa[i][1], adq, bq0.y);
                    ffma2(qa[i][2], adq, bq1.x);
                    ffma2(qa[i][3], adq, bq1.y);
                    unsigned long long adk = dup2(a[i+1]);
                    ffma2(ka[i][0], adk, bk0.x);
                    ffma2(ka[i][1], adk, bk0.y);
                    ffma2(ka[i][2], adk, bk1.x);
                    ffma2(ka[i][3], adk, bk1.y);
                }
            }
        }
        // fold e-tile accumulators into per-row scalars
#pragma unroll
        for (int i=0;i<8;i++){
#pragma unroll
            for (int j=0;j<4;j++){
                F2U qu; qu.u = qa[i][j];
                F2U ku; ku.u = ka[i][j];
                qq[i] = fmaf(qu.f.x, qu.f.x, fmaf(qu.f.y, qu.f.y, qq[i]));
                kk[i] = fmaf(ku.f.x, ku.f.x, fmaf(ku.f.y, ku.f.y, kk[i]));
                qk[i] = fmaf(qu.f.x, ku.f.x, fmaf(qu.f.y, ku.f.y, qk[i]));
            }
        }
    }

    // cross-thread reduction over the 16 e-subtiles (reuse smem)
    __syncthreads();
#pragma unroll
    for (int i=0;i<8;i++){
        sm[0*2048 + (row0+i)*16 + tx] = qq[i];
        sm[1*2048 + (row0+i)*16 + tx] = kk[i];
        sm[2*2048 + (row0+i)*16 + tx] = qk[i];
    }
    __syncthreads();
    if (tid < 128) {
        float sqq=0.f, skk=0.f, sqk=0.f;
#pragma unroll
        for (int x=0;x<16;x++){
            sqq += sm[0*2048 + tid*16 + x];
            skk += sm[1*2048 + tid*16 + x];
            sqk += sm[2*2048 + tid*16 + x];
        }
        int t = tt0 + tid;          // cos index (q row t, k row t+1)
        if (t < LL-1) {
            float denom = fmaxf(sqrtf(sqq), 1e-12f) * fmaxf(sqrtf(skk), 1e-12f);
            float cosv  = sqk / denom;
            float p = fminf(fmaxf((1.f - cosv)*0.5f, 0.f), 1.f);
            g_prob[b*LL + t + 1] = p;
        }
        if (tt0 == 0 && tid == 0) g_prob[b*LL] = 1.0f;
    }
}

// ---------------- K2: mask scan / compaction indices ----------------
__global__ __launch_bounds__(1024)
void k_scan()
{
    const int b = blockIdx.x;
    const int tid = threadIdx.x;
    __shared__ int wsum[32];

    const int base = b*LL + tid*4;
    float p[4]; int m[4]; int s = 0;
#pragma unroll
    for (int i=0;i<4;i++){
        p[i] = g_prob[base+i];
        m[i] = p[i] > 0.5f ? 1 : 0;
        s += m[i];
    }
    const int lane = tid & 31, wid = tid >> 5;
    int incl = s;
#pragma unroll
    for (int o=1;o<32;o<<=1){
        int v = __shfl_up_sync(0xffffffffu, incl, o);
        if (lane >= o) incl += v;
    }
    if (lane == 31) wsum[wid] = incl;
    __syncthreads();
    if (tid < 32) {
        int v = wsum[tid];
        int iv = v;
#pragma unroll
        for (int o=1;o<32;o<<=1){
            int u = __shfl_up_sync(0xffffffffu, iv, o);
            if (tid >= o) iv += u;
        }
        wsum[tid] = iv - v;   // exclusive
    }
    __syncthreads();
    int run = incl - s + wsum[wid];   // exclusive prefix for this thread
#pragma unroll
    for (int i=0;i<4;i++){
        if (m[i]) {
            g_src[b*LL + run]   = tid*4 + i;
            g_decay[b*LL + run] = fminf(fmaxf(1.f - p[i], 0.f), 1.f);
            run++;
        }
        g_cidx[base + i] = run - 1;
    }
    if (tid == 1023) g_counts[b] = run;
}

// ---------------- K3: EMA recurrence over chunks ----------------
__global__ __launch_bounds__(128)
void k_ema(const float* __restrict__ hid, const float* __restrict__ init)
{
    const int b = blockIdx.y;
    const int d = blockIdx.x * 128 + threadIdx.x;
    const float* hb = hid + (size_t)b*LL*DD;
    float state = init[b*DD + d];
    const int n = g_counts[b];
    const int*   src = g_src   + b*LL;
    const float* dec = g_decay + b*LL;
    float* emab = g_ema + (size_t)b*LL*DD;
    for (int j = 0; j < n; ++j) {
        int   t = __ldg(src + j);
        float a = __ldg(dec + j);
        float x = __ldg(hb + (size_t)t*DD + d);
        state = a*state + (1.f - a)*x;
        emab[(size_t)j*DD + d] = state;
    }
}

// ---------------- K4: broadcast back + residual ----------------
__global__ __launch_bounds__(256)
void k_out(const float* __restrict__ res, float* __restrict__ out)
{
    size_t gid  = (size_t)blockIdx.x * 256 + threadIdx.x;
    size_t flat = gid * 4;
    int d = (int)(flat & (DD-1));
    int t = (int)((flat >> 10) & (LL-1));
    int b = (int)(flat >> 22);
    int ci = g_cidx[b*LL + t];
    float4 r = *(const float4*)(res + flat);
    float4 e = *(const float4*)(g_ema + ((size_t)(b*LL + ci))*DD + d);
    float4 o = make_float4(r.x+e.x, r.y+e.y, r.z+e.z, r.w+e.w);
    *(float4*)(out + flat) = o;
}

// ---------------- launch ----------------
extern "C" void kernel_launch(void* const* d_in, const int* in_sizes, int n_in,
                              void* d_out, int out_size)
{
    const float* hid = (const float*)d_in[0];
    const float* res = (const float*)d_in[1];
    const float* wq  = (const float*)d_in[2];
    const float* wk  = (const float*)d_in[3];
    const float* ini = (const float*)d_in[4];
    float* out = (float*)d_out;

    k_router<<<dim3(32, BB), 256>>>(hid, wq, wk);
    k_scan  <<<BB, 1024>>>();
    k_ema   <<<dim3(DD/128, BB), 128>>>(hid, ini);
    k_out   <<<(BB*LL*DD/4 + 255)/256, 256>>>(res, out);
}

// round 2
// speedup vs baseline: 1.2257x; 1.2257x over previous
#include <cuda_runtime.h>
#include <cstdint>

#define BB 4
#define LL 4096
#define DD 1024
#define HT (BB*LL)   // hidT row length

// ---------------- scratch (static device globals; no allocation) ----------------
__device__ float g_prob[BB*LL];
__device__ float g_decay[BB*LL];
__device__ int   g_src[BB*LL];
__device__ int   g_cidx[BB*LL];
__device__ int   g_counts[BB];
__device__ float g_ema[(size_t)BB*LL*DD];          // 64 MB
__device__ float g_hidT[(size_t)DD*HT + 1024];     // 64 MB (+pad), [d][b*LL+t]
__device__ float g_wqT[(size_t)DD*DD];             // [d][e]
__device__ float g_wkT[(size_t)DD*DD];

// ---------------- K0: tiled transpose (in R x C -> out C x R) ----------------
__global__ __launch_bounds__(256)
void k_tr(const float* __restrict__ in, float* __restrict__ out, int R, int C)
{
    __shared__ float tile[32][33];
    const int c0 = blockIdx.x * 32;
    const int r0 = blockIdx.y * 32;
    const int x = threadIdx.x, y = threadIdx.y;   // 32 x 8
#pragma unroll
    for (int j = 0; j < 32; j += 8)
        tile[y + j][x] = in[(size_t)(r0 + y + j) * C + c0 + x];
    __syncthreads();
#pragma unroll
    for (int j = 0; j < 32; j += 8)
        out[(size_t)(c0 + y + j) * R + r0 + x] = tile[x][y + j];
}

// ---------------- K1: fused router GEMM -> prob ----------------
#define BK 32
#define ASTR 136            // As row stride (floats)
#define BSTR 132            // Bq/Bk row stride (floats)
#define STAGE_F (BK*ASTR + 2*BK*BSTR)   // 12800 floats per stage
#define OFF_BQ (BK*ASTR)                // 4352
#define OFF_BK (BK*ASTR + BK*BSTR)      // 8576

union F2U { unsigned long long u; float2 f; };

__device__ __forceinline__ unsigned long long dup2(float a){
    unsigned long long r;
    asm("mov.b64 %0, {%1, %1};" : "=l"(r) : "r"(__float_as_uint(a)));
    return r;
}
__device__ __forceinline__ void ffma2(unsigned long long& d, unsigned long long a, unsigned long long b){
    asm("fma.rn.f32x2 %0, %1, %2, %0;" : "+l"(d) : "l"(a), "l"(b));
}
__device__ __forceinline__ void cpa16(float* dst, const float* src){
    unsigned d = (unsigned)__cvta_generic_to_shared(dst);
    asm volatile("cp.async.cg.shared.global [%0], [%1], 16;\n" :: "r"(d), "l"(src));
}

__device__ __forceinline__ void issue_stage(float* sb, size_t bLLt0, int e0, int kc, int tid)
{
    float* As = sb;
    float* Bq = sb + OFF_BQ;
    float* Bk = sb + OFF_BK;
    // A: 32 k-rows x 33 float4 (132 floats, covers tokens t0..t0+131)
    for (int v = tid; v < 32*33; v += 256) {
        int k = v / 33;
        int f = (v - k*33) << 2;
        cpa16(As + k*ASTR + f, g_hidT + (size_t)(kc + k)*HT + bLLt0 + f);
    }
    // Bq/Bk: 32 k-rows x 32 float4 each
    for (int v = tid; v < 32*32; v += 256) {
        int k = v >> 5;
        int f = (v & 31) << 2;
        size_t so = (size_t)(kc + k)*DD + e0 + f;
        cpa16(Bq + k*BSTR + f, g_wqT + so);
        cpa16(Bk + k*BSTR + f, g_wkT + so);
    }
}

extern __shared__ float dsm[];

__global__ __launch_bounds__(256, 1)
void k_router()
{
    const int b   = blockIdx.y;
    const int tt0 = blockIdx.x * 128;
    const size_t bLLt0 = (size_t)b*LL + tt0;

    const int tid  = threadIdx.x;
    const int tx   = tid & 15;
    const int ty   = tid >> 4;
    const int row0 = ty * 8;
    const int e0l  = tx * 8;

    float qq[8], kk[8], qk[8];
#pragma unroll
    for (int i=0;i<8;i++){ qq[i]=0.f; kk[i]=0.f; qk[i]=0.f; }

    for (int et = 0; et < DD/128; ++et) {
        const int e0 = et * 128;
        unsigned long long qa[8][4], ka[8][4];
#pragma unroll
        for (int i=0;i<8;i++)
#pragma unroll
            for (int j=0;j<4;j++){ qa[i][j]=0ull; ka[i][j]=0ull; }

        issue_stage(dsm, bLLt0, e0, 0, tid);
        asm volatile("cp.async.commit_group;\n");

        const int NCH = DD / BK;  // 32
        for (int s = 0; s < NCH; ++s) {
            if (s + 1 < NCH) {
                issue_stage(dsm + ((s+1)&1)*STAGE_F, bLLt0, e0, (s+1)*BK, tid);
                asm volatile("cp.async.commit_group;\n");
                asm volatile("cp.async.wait_group 1;\n");
            } else {
                asm volatile("cp.async.wait_group 0;\n");
            }
            __syncthreads();

            float* sb = dsm + (s&1)*STAGE_F;
            const float* As = sb;
            const float* Bq = sb + OFF_BQ;
            const float* Bk = sb + OFF_BK;

#pragma unroll
            for (int k = 0; k < BK; ++k) {
                const float* arow = As + k*ASTR;
                float4 av0 = *(const float4*)(arow + row0);
                float4 av1 = *(const float4*)(arow + row0 + 4);
                float a8   = arow[row0 + 8];
                float a[9] = {av0.x,av0.y,av0.z,av0.w,av1.x,av1.y,av1.z,av1.w,a8};

                ulonglong2 bq0 = *(const ulonglong2*)(Bq + k*BSTR + e0l);
                ulonglong2 bq1 = *(const ulonglong2*)(Bq + k*BSTR + e0l + 4);
                ulonglong2 bk0 = *(const ulonglong2*)(Bk + k*BSTR + e0l);
                ulonglong2 bk1 = *(const ulonglong2*)(Bk + k*BSTR + e0l + 4);
#pragma unroll
                for (int i=0;i<8;i++){
                    unsigned long long adq = dup2(a[i]);
                    ffma2(qa[i][0], adq, bq0.x);
                    ffma2(qa[i][1], adq, bq0.y);
                    ffma2(qa[i][2], adq, bq1.x);
                    ffma2(qa[i][3], adq, bq1.y);
                    unsigned long long adk = dup2(a[i+1]);
                    ffma2(ka[i][0], adk, bk0.x);
                    ffma2(ka[i][1], adk, bk0.y);
                    ffma2(ka[i][2], adk, bk1.x);
                    ffma2(ka[i][3], adk, bk1.y);
                }
            }
            __syncthreads();
        }

        // fold e-tile accumulators into per-row scalars
#pragma unroll
        for (int i=0;i<8;i++){
#pragma unroll
            for (int j=0;j<4;j++){
                F2U qu; qu.u = qa[i][j];
                F2U ku; ku.u = ka[i][j];
                qq[i] = fmaf(qu.f.x, qu.f.x, fmaf(qu.f.y, qu.f.y, qq[i]));
                kk[i] = fmaf(ku.f.x, ku.f.x, fmaf(ku.f.y, ku.f.y, kk[i]));
                qk[i] = fmaf(qu.f.x, ku.f.x, fmaf(qu.f.y, ku.f.y, qk[i]));
            }
        }
    }

    // cross-thread reduction over the 16 e-subtiles (reuse dynamic smem)
    __syncthreads();
#pragma unroll
    for (int i=0;i<8;i++){
        dsm[0*2048 + (row0+i)*16 + tx] = qq[i];
        dsm[1*2048 + (row0+i)*16 + tx] = kk[i];
        dsm[2*2048 + (row0+i)*16 + tx] = qk[i];
    }
    __syncthreads();
    if (tid < 128) {
        float sqq=0.f, skk=0.f, sqk=0.f;
#pragma unroll
        for (int x=0;x<16;x++){
            sqq += dsm[0*2048 + tid*16 + x];
            skk += dsm[1*2048 + tid*16 + x];
            sqk += dsm[2*2048 + tid*16 + x];
        }
        int t = tt0 + tid;          // cos index (q row t, k row t+1)
        if (t < LL-1) {
            float denom = fmaxf(sqrtf(sqq), 1e-12f) * fmaxf(sqrtf(skk), 1e-12f);
            float cosv  = sqk / denom;
            float p = fminf(fmaxf((1.f - cosv)*0.5f, 0.f), 1.f);
            g_prob[b*LL + t + 1] = p;
        }
        if (tt0 == 0 && tid == 0) g_prob[b*LL] = 1.0f;
    }
}

// ---------------- K2: mask scan / compaction indices ----------------
__global__ __launch_bounds__(1024)
void k_scan()
{
    const int b = blockIdx.x;
    const int tid = threadIdx.x;
    __shared__ int wsum[32];

    const int base = b*LL + tid*4;
    float p[4]; int m[4]; int s = 0;
#pragma unroll
    for (int i=0;i<4;i++){
        p[i] = g_prob[base+i];
        m[i] = p[i] > 0.5f ? 1 : 0;
        s += m[i];
    }
    const int lane = tid & 31, wid = tid >> 5;
    int incl = s;
#pragma unroll
    for (int o=1;o<32;o<<=1){
        int v = __shfl_up_sync(0xffffffffu, incl, o);
        if (lane >= o) incl += v;
    }
    if (lane == 31) wsum[wid] = incl;
    __syncthreads();
    if (tid < 32) {
        int v = wsum[tid];
        int iv = v;
#pragma unroll
        for (int o=1;o<32;o<<=1){
            int u = __shfl_up_sync(0xffffffffu, iv, o);
            if (tid >= o) iv += u;
        }
        wsum[tid] = iv - v;   // exclusive
    }
    __syncthreads();
    int run = incl - s + wsum[wid];   // exclusive prefix for this thread
#pragma unroll
    for (int i=0;i<4;i++){
        if (m[i]) {
            g_src[b*LL + run]   = tid*4 + i;
            g_decay[b*LL + run] = fminf(fmaxf(1.f - p[i], 0.f), 1.f);
            run++;
        }
        g_cidx[base + i] = run - 1;
    }
    if (tid == 1023) g_counts[b] = run;
}

// ---------------- K3: EMA recurrence over chunks ----------------
__global__ __launch_bounds__(128)
void k_ema(const float* __restrict__ hid, const float* __restrict__ init)
{
    const int b = blockIdx.y;
    const int d = blockIdx.x * 128 + threadIdx.x;
    const float* hb = hid + (size_t)b*LL*DD;
    float state = init[b*DD + d];
    const int n = g_counts[b];
    const int*   src = g_src   + b*LL;
    const float* dec = g_decay + b*LL;
    float* emab = g_ema + (size_t)b*LL*DD;
    for (int j = 0; j < n; ++j) {
        int   t = __ldg(src + j);
        float a = __ldg(dec + j);
        float x = __ldg(hb + (size_t)t*DD + d);
        state = a*state + (1.f - a)*x;
        emab[(size_t)j*DD + d] = state;
    }
}

// ---------------- K4: broadcast back + residual ----------------
__global__ __launch_bounds__(256)
void k_out(const float* __restrict__ res, float* __restrict__ out)
{
    size_t gid  = (size_t)blockIdx.x * 256 + threadIdx.x;
    size_t flat = gid * 4;
    int d = (int)(flat & (DD-1));
    int t = (int)((flat >> 10) & (LL-1));
    int b = (int)(flat >> 22);
    int ci = g_cidx[b*LL + t];
    float4 r = *(const float4*)(res + flat);
    float4 e = *(const float4*)(g_ema + ((size_t)(b*LL + ci))*DD + d);
    float4 o = make_float4(r.x+e.x, r.y+e.y, r.z+e.z, r.w+e.w);
    *(float4*)(out + flat) = o;
}

// ---------------- launch ----------------
extern "C" void kernel_launch(void* const* d_in, const int* in_sizes, int n_in,
                              void* d_out, int out_size)
{
    const float* hid = (const float*)d_in[0];
    const float* res = (const float*)d_in[1];
    const float* wq  = (const float*)d_in[2];
    const float* wk  = (const float*)d_in[3];
    const float* ini = (const float*)d_in[4];
    float* out = (float*)d_out;

    float* hidT; cudaGetSymbolAddress((void**)&hidT, g_hidT);
    float* wqT;  cudaGetSymbolAddress((void**)&wqT,  g_wqT);
    float* wkT;  cudaGetSymbolAddress((void**)&wkT,  g_wkT);

    static bool attr_done = false;
    if (!attr_done) {
        cudaFuncSetAttribute(k_router, cudaFuncAttributeMaxDynamicSharedMemorySize,
                             2*STAGE_F*(int)sizeof(float));
        attr_done = true;
    }

    // transposes: hid (16384 x 1024) -> hidT; weights (1024 x 1024) -> wT
    k_tr<<<dim3(DD/32, HT/32), dim3(32,8)>>>(hid, hidT, HT, DD);
    k_tr<<<dim3(DD/32, DD/32), dim3(32,8)>>>(wq,  wqT,  DD, DD);
    k_tr<<<dim3(DD/32, DD/32), dim3(32,8)>>>(wk,  wkT,  DD, DD);

    k_router<<<dim3(32, BB), 256, 2*STAGE_F*(int)sizeof(float)>>>();
    k_scan  <<<BB, 1024>>>();
    k_ema   <<<dim3(DD/128, BB), 128>>>(hid, ini);
    k_out   <<<(BB*LL*DD/4 + 255)/256, 256>>>(res, out);
}

// round 7
// speedup vs baseline: 1.2283x; 1.0022x over previous
#include <cuda_runtime.h>
#include <cstdint>

#define BB 4
#define LL 4096
#define DD 1024
#define HT (BB*LL)   // hidT row length

// ---------------- scratch (static device globals; no allocation) ----------------
__device__ float g_prob[BB*LL];
__device__ float g_decay[BB*LL];
__device__ int   g_src[BB*LL];
__device__ int   g_cidx[BB*LL];
__device__ int   g_counts[BB];
__device__ float g_ema[(size_t)BB*LL*DD];          // 64 MB
__device__ float g_hidT[(size_t)DD*HT + 1024];     // 64 MB (+pad), [d][b*LL+t]
__device__ float g_wqT[(size_t)DD*DD];             // [d][e]
__device__ float g_wkT[(size_t)DD*DD];

// ---------------- K0: tiled transpose (in R x C -> out C x R) ----------------
__global__ __launch_bounds__(256)
void k_tr(const float* __restrict__ in, float* __restrict__ out, int R, int C)
{
    __shared__ float tile[32][33];
    const int c0 = blockIdx.x * 32;
    const int r0 = blockIdx.y * 32;
    const int x = threadIdx.x, y = threadIdx.y;   // 32 x 8
#pragma unroll
    for (int j = 0; j < 32; j += 8)
        tile[y + j][x] = in[(size_t)(r0 + y + j) * C + c0 + x];
    __syncthreads();
#pragma unroll
    for (int j = 0; j < 32; j += 8)
        out[(size_t)(c0 + y + j) * R + r0 + x] = tile[x][y + j];
}

// ---------------- K1: fused router GEMM -> prob ----------------
#define BK 32
#define ASTR 136            // As row stride (floats)
#define BSTR 132            // Bq/Bk row stride (floats)
#define STAGE_F (BK*ASTR + 2*BK*BSTR)   // 12800 floats per stage
#define OFF_BQ (BK*ASTR)                // 4352
#define OFF_BK (BK*ASTR + BK*BSTR)      // 8576

union F2U { unsigned long long u; float2 f; };

__device__ __forceinline__ unsigned long long dup2(float a){
    unsigned long long r;
    asm("mov.b64 %0, {%1, %1};" : "=l"(r) : "r"(__float_as_uint(a)));
    return r;
}
__device__ __forceinline__ void ffma2(unsigned long long& d, unsigned long long a, unsigned long long b){
    asm("fma.rn.f32x2 %0, %1, %2, %0;" : "+l"(d) : "l"(a), "l"(b));
}
__device__ __forceinline__ void cpa16(float* dst, const float* src){
    unsigned d = (unsigned)__cvta_generic_to_shared(dst);
    asm volatile("cp.async.cg.shared.global [%0], [%1], 16;\n" :: "r"(d), "l"(src));
}

__device__ __forceinline__ void issue_stage(float* sb, size_t bLLt0, int e0, int kc, int tid)
{
    float* As = sb;
    float* Bq = sb + OFF_BQ;
    float* Bk = sb + OFF_BK;
    // A: 32 k-rows x 33 float4 (132 floats, covers tokens t0..t0+131)
    for (int v = tid; v < 32*33; v += 256) {
        int k = v / 33;
        int f = (v - k*33) << 2;
        cpa16(As + k*ASTR + f, g_hidT + (size_t)(kc + k)*HT + bLLt0 + f);
    }
    // Bq/Bk: 32 k-rows x 32 float4 each
    for (int v = tid; v < 32*32; v += 256) {
        int k = v >> 5;
        int f = (v & 31) << 2;
        size_t so = (size_t)(kc + k)*DD + e0 + f;
        cpa16(Bq + k*BSTR + f, g_wqT + so);
        cpa16(Bk + k*BSTR + f, g_wkT + so);
    }
}

extern __shared__ float dsm[];

__global__ __launch_bounds__(256, 1)
void k_router()
{
    const int b   = blockIdx.y;
    const int tt0 = blockIdx.x * 128;
    const size_t bLLt0 = (size_t)b*LL + tt0;

    const int tid  = threadIdx.x;
    const int tx   = tid & 15;
    const int ty   = tid >> 4;
    const int row0 = ty * 8;
    const int e0l  = tx * 8;

    float qq[8], kk[8], qk[8];
#pragma unroll
    for (int i=0;i<8;i++){ qq[i]=0.f; kk[i]=0.f; qk[i]=0.f; }

    for (int et = 0; et < DD/128; ++et) {
        const int e0 = et * 128;
        unsigned long long qa[8][4], ka[8][4];
#pragma unroll
        for (int i=0;i<8;i++)
#pragma unroll
            for (int j=0;j<4;j++){ qa[i][j]=0ull; ka[i][j]=0ull; }

        issue_stage(dsm, bLLt0, e0, 0, tid);
        asm volatile("cp.async.commit_group;\n");

        const int NCH = DD / BK;  // 32
        for (int s = 0; s < NCH; ++s) {
            if (s + 1 < NCH) {
                issue_stage(dsm + ((s+1)&1)*STAGE_F, bLLt0, e0, (s+1)*BK, tid);
                asm volatile("cp.async.commit_group;\n");
                asm volatile("cp.async.wait_group 1;\n");
            } else {
                asm volatile("cp.async.wait_group 0;\n");
            }
            __syncthreads();

            float* sb = dsm + (s&1)*STAGE_F;
            const float* As = sb;
            const float* Bq = sb + OFF_BQ;
            const float* Bk = sb + OFF_BK;

#pragma unroll
            for (int k = 0; k < BK; ++k) {
                const float* arow = As + k*ASTR;
                float4 av0 = *(const float4*)(arow + row0);
                float4 av1 = *(const float4*)(arow + row0 + 4);
                float a8   = arow[row0 + 8];
                float a[9] = {av0.x,av0.y,av0.z,av0.w,av1.x,av1.y,av1.z,av1.w,a8};

                ulonglong2 bq0 = *(const ulonglong2*)(Bq + k*BSTR + e0l);
                ulonglong2 bq1 = *(const ulonglong2*)(Bq + k*BSTR + e0l + 4);
                ulonglong2 bk0 = *(const ulonglong2*)(Bk + k*BSTR + e0l);
                ulonglong2 bk1 = *(const ulonglong2*)(Bk + k*BSTR + e0l + 4);
#pragma unroll
                for (int i=0;i<8;i++){
                    unsigned long long adq = dup2(a[i]);
                    ffma2(qa[i][0], adq, bq0.x);
                    ffma2(qa[i][1], adq, bq0.y);
                    ffma2(qa[i][2], adq, bq1.x);
                    ffma2(qa[i][3], adq, bq1.y);
                    unsigned long long adk = dup2(a[i+1]);
                    ffma2(ka[i][0], adk, bk0.x);
                    ffma2(ka[i][1], adk, bk0.y);
                    ffma2(ka[i][2], adk, bk1.x);
                    ffma2(ka[i][3], adk, bk1.y);
                }
            }
            __syncthreads();
        }

        // fold e-tile accumulators into per-row scalars
#pragma unroll
        for (int i=0;i<8;i++){
#pragma unroll
            for (int j=0;j<4;j++){
                F2U qu; qu.u = qa[i][j];
                F2U ku; ku.u = ka[i][j];
                qq[i] = fmaf(qu.f.x, qu.f.x, fmaf(qu.f.y, qu.f.y, qq[i]));
                kk[i] = fmaf(ku.f.x, ku.f.x, fmaf(ku.f.y, ku.f.y, kk[i]));
                qk[i] = fmaf(qu.f.x, ku.f.x, fmaf(qu.f.y, ku.f.y, qk[i]));
            }
        }
    }

    // cross-thread reduction over the 16 e-subtiles (reuse dynamic smem)
    __syncthreads();
#pragma unroll
    for (int i=0;i<8;i++){
        dsm[0*2048 + (row0+i)*16 + tx] = qq[i];
        dsm[1*2048 + (row0+i)*16 + tx] = kk[i];
        dsm[2*2048 + (row0+i)*16 + tx] = qk[i];
    }
    __syncthreads();
    if (tid < 128) {
        float sqq=0.f, skk=0.f, sqk=0.f;
#pragma unroll
        for (int x=0;x<16;x++){
            sqq += dsm[0*2048 + tid*16 + x];
            skk += dsm[1*2048 + tid*16 + x];
            sqk += dsm[2*2048 + tid*16 + x];
        }
        int t = tt0 + tid;          // cos index (q row t, k row t+1)
        if (t < LL-1) {
            float denom = fmaxf(sqrtf(sqq), 1e-12f) * fmaxf(sqrtf(skk), 1e-12f);
            float cosv  = sqk / denom;
            float p = fminf(fmaxf((1.f - cosv)*0.5f, 0.f), 1.f);
            g_prob[b*LL + t + 1] = p;
        }
        if (tt0 == 0 && tid == 0) g_prob[b*LL] = 1.0f;
    }
}

// ---------------- K2: mask scan / compaction indices ----------------
__global__ __launch_bounds__(1024)
void k_scan()
{
    const int b = blockIdx.x;
    const int tid = threadIdx.x;
    __shared__ int wsum[32];

    const int base = b*LL + tid*4;
    float p[4]; int m[4]; int s = 0;
#pragma unroll
    for (int i=0;i<4;i++){
        p[i] = g_prob[base+i];
        m[i] = p[i] > 0.5f ? 1 : 0;
        s += m[i];
    }
    const int lane = tid & 31, wid = tid >> 5;
    int incl = s;
#pragma unroll
    for (int o=1;o<32;o<<=1){
        int v = __shfl_up_sync(0xffffffffu, incl, o);
        if (lane >= o) incl += v;
    }
    if (lane == 31) wsum[wid] = incl;
    __syncthreads();
    if (tid < 32) {
        int v = wsum[tid];
        int iv = v;
#pragma unroll
        for (int o=1;o<32;o<<=1){
            int u = __shfl_up_sync(0xffffffffu, iv, o);
            if (tid >= o) iv += u;
        }
        wsum[tid] = iv - v;   // exclusive
    }
    __syncthreads();
    int run = incl - s + wsum[wid];   // exclusive prefix for this thread
#pragma unroll
    for (int i=0;i<4;i++){
        if (m[i]) {
            g_src[b*LL + run]   = tid*4 + i;
            g_decay[b*LL + run] = fminf(fmaxf(1.f - p[i], 0.f), 1.f);
            run++;
        }
        g_cidx[base + i] = run - 1;
    }
    if (tid == 1023) g_counts[b] = run;
}

// ---------------- K3: EMA recurrence over chunks ----------------
__global__ __launch_bounds__(128)
void k_ema(const float* __restrict__ hid, const float* __restrict__ init)
{
    const int b = blockIdx.y;
    const int d = blockIdx.x * 128 + threadIdx.x;
    const float* hb = hid + (size_t)b*LL*DD;
    float state = init[b*DD + d];
    const int n = g_counts[b];
    const int*   src = g_src   + b*LL;
    const float* dec = g_decay + b*LL;
    float* emab = g_ema + (size_t)b*LL*DD;
    for (int j = 0; j < n; ++j) {
        int   t = __ldg(src + j);
        float a = __ldg(dec + j);
        float x = __ldg(hb + (size_t)t*DD + d);
        state = a*state + (1.f - a)*x;
        emab[(size_t)j*DD + d] = state;
    }
}

// ---------------- K4: broadcast back + residual ----------------
__global__ __launch_bounds__(256)
void k_out(const float* __restrict__ res, float* __restrict__ out)
{
    size_t gid  = (size_t)blockIdx.x * 256 + threadIdx.x;
    size_t flat = gid * 4;
    int d = (int)(flat & (DD-1));
    int t = (int)((flat >> 10) & (LL-1));
    int b = (int)(flat >> 22);
    int ci = g_cidx[b*LL + t];
    float4 r = *(const float4*)(res + flat);
    float4 e = *(const float4*)(g_ema + ((size_t)(b*LL + ci))*DD + d);
    float4 o = make_float4(r.x+e.x, r.y+e.y, r.z+e.z, r.w+e.w);
    *(float4*)(out + flat) = o;
}

// ---------------- launch ----------------
extern "C" void kernel_launch(void* const* d_in, const int* in_sizes, int n_in,
                              void* d_out, int out_size)
{
    const float* hid = (const float*)d_in[0];
    const float* res = (const float*)d_in[1];
    const float* wq  = (const float*)d_in[2];
    const float* wk  = (const float*)d_in[3];
    const float* ini = (const float*)d_in[4];
    float* out = (float*)d_out;

    float* hidT; cudaGetSymbolAddress((void**)&hidT, g_hidT);
    float* wqT;  cudaGetSymbolAddress((void**)&wqT,  g_wqT);
    float* wkT;  cudaGetSymbolAddress((void**)&wkT,  g_wkT);

    static bool attr_done = false;
    if (!attr_done) {
        cudaFuncSetAttribute(k_router, cudaFuncAttributeMaxDynamicSharedMemorySize,
                             2*STAGE_F*(int)sizeof(float));
        attr_done = true;
    }

    // transposes: hid (16384 x 1024) -> hidT; weights (1024 x 1024) -> wT
    k_tr<<<dim3(DD/32, HT/32), dim3(32,8)>>>(hid, hidT, HT, DD);
    k_tr<<<dim3(DD/32, DD/32), dim3(32,8)>>>(wq,  wqT,  DD, DD);
    k_tr<<<dim3(DD/32, DD/32), dim3(32,8)>>>(wk,  wkT,  DD, DD);

    k_router<<<dim3(32, BB), 256, 2*STAGE_F*(int)sizeof(float)>>>();
    k_scan  <<<BB, 1024>>>();
    k_ema   <<<dim3(DD/128, BB), 128>>>(hid, ini);
    k_out   <<<(BB*LL*DD/4 + 255)/256, 256>>>(res, out);
}

// round 10
// speedup vs baseline: 1.7957x; 1.4619x over previous
#include <cuda_runtime.h>
#include <cstdint>

#define BB 4
#define LL 4096
#define DD 1024
#define HT (BB*LL)
#define FCAP 4096
#define BANDC 5e-4f

// ---------------- scratch (static device globals; zero-initialized) ----------------
__device__ float g_prob[BB*LL];
__device__ float g_invnn[BB*LL];
__device__ float g_decay[BB*LL];
__device__ int   g_src[BB*LL];
__device__ int   g_cidx[BB*LL];
__device__ int   g_counts[BB];
__device__ int   g_fcnt;
__device__ int   g_flist[FCAP];
__device__ float g_qkpart[FCAP*8];
__device__ float g_ema[(size_t)BB*LL*DD];      // 64 MB
__device__ float g_xr[(size_t)(HT+136)*DD];    // rounded X; rows >= HT stay zero
__device__ float g_wqr[(size_t)DD*DD];
__device__ float g_wkr[(size_t)DD*DD];

// ---------------- helpers ----------------
__device__ __forceinline__ float tf32r(float x){
    uint32_t u; asm("cvt.rna.tf32.f32 %0, %1;" : "=r"(u) : "f"(x));
    return __uint_as_float(u);
}
__device__ __forceinline__ void cpa16s(uint32_t daddr, const float* src){
    asm volatile("cp.async.cg.shared.global [%0], [%1], 16;" :: "r"(daddr), "l"(src));
}
__device__ __forceinline__ void mma8(float* d, const uint32_t* a, const uint32_t* b){
    asm("mma.sync.aligned.m16n8k8.row.col.f32.tf32.tf32.f32 "
        "{%0,%1,%2,%3}, {%4,%5,%6,%7}, {%8,%9}, {%0,%1,%2,%3};"
        : "+f"(d[0]), "+f"(d[1]), "+f"(d[2]), "+f"(d[3])
        : "r"(a[0]), "r"(a[1]), "r"(a[2]), "r"(a[3]), "r"(b[0]), "r"(b[1]));
}

// ---------------- K0: round fp32 -> tf32(RNA) ----------------
__global__ __launch_bounds__(256)
void k_round(const float* __restrict__ in, float* __restrict__ out, int n4)
{
    int i = blockIdx.x*256 + threadIdx.x;
    if (i >= n4) return;
    float4 x = ((const float4*)in)[i];
    float4 h;
    h.x = tf32r(x.x); h.y = tf32r(x.y); h.z = tf32r(x.z); h.w = tf32r(x.w);
    ((float4*)out)[i] = h;
}
__global__ void k_zero(){ g_fcnt = 0; }

// ---------------- K1: HMMA tf32 router ----------------
// stage: A 129 rows (pad 132) x 32k, stride 36 ; B 256 rows (Wq128 + Wk128) x 32k, stride 36
#define ASZ_FL (132*36)                 // 4752 floats
#define STG_FL (ASZ_FL + 256*36)        // 13968 floats
#define RSMEM  (2*STG_FL*4)             // 111744 bytes

__device__ __forceinline__ void ld_stage(uint32_t sbb, size_t arow0, int e0, int kc, int tid)
{
    for (int v = tid; v < 3080; v += 256){
        const float* src;
        uint32_t dst;
        if (v < 1032){                       // A: 129 rows x 8 float4
            int row = v >> 3, kg = v & 7;
            src = g_xr + (arow0 + (size_t)row)*DD + kc + kg*4;
            dst = (uint32_t)(row*36 + kg*4);
        } else {                             // B: 256 rows x 8 float4
            int u = v - 1032;
            int row = u >> 3, kg = u & 7;
            const float* w = (row < 128) ? g_wqr : g_wkr;
            src = w + (size_t)(e0 + (row & 127))*DD + kc + kg*4;
            dst = (uint32_t)(ASZ_FL + row*36 + kg*4);
        }
        cpa16s(sbb + dst*4u, src);
    }
}

extern __shared__ float dsm[];

__global__ __launch_bounds__(256, 1)
void k_rmma()
{
    const int b   = blockIdx.y;
    const int t0  = blockIdx.x * 128;
    const int tid = threadIdx.x;
    const int wid = tid >> 5, lane = tid & 31;
    const int warp_m = wid & 3, warp_n = wid >> 2;
    const int rm = warp_m*32, rn = warp_n*64;
    const int grp = lane >> 2, c = lane & 3;
    const size_t arow0 = (size_t)b*LL + t0;
    const uint32_t sbb = (uint32_t)__cvta_generic_to_shared(dsm);

    float qq[4], kk[4], qk[4];
#pragma unroll
    for (int i=0;i<4;i++){ qq[i]=0.f; kk[i]=0.f; qk[i]=0.f; }

    for (int ep = 0; ep < 8; ++ep){
        const int e0 = ep*128;
        float dq[2][8][4], dk[2][8][4];
#pragma unroll
        for (int fm=0; fm<2; fm++)
#pragma unroll
            for (int fn=0; fn<8; fn++)
#pragma unroll
                for (int r=0; r<4; r++){ dq[fm][fn][r]=0.f; dk[fm][fn][r]=0.f; }

        ld_stage(sbb, arow0, e0, 0, tid);
        asm volatile("cp.async.commit_group;" ::: "memory");

        for (int ch = 0; ch < 32; ++ch){
            if (ch + 1 < 32){
                ld_stage(sbb + (uint32_t)(((ch+1)&1)*STG_FL*4), arow0, e0, (ch+1)*32, tid);
                asm volatile("cp.async.commit_group;" ::: "memory");
                asm volatile("cp.async.wait_group 1;" ::: "memory");
            } else {
                asm volatile("cp.async.wait_group 0;" ::: "memory");
            }
            __syncthreads();

            const float* As = dsm + (ch&1)*STG_FL;
            const float* Bs = As + ASZ_FL;

#pragma unroll
            for (int k8 = 0; k8 < 4; ++k8){
                const int kb = k8*8;
                uint32_t aq[2][4], ak[2][4];
#pragma unroll
                for (int fm = 0; fm < 2; ++fm){
                    int r = rm + fm*16 + grp;
                    aq[fm][0] = __float_as_uint(As[(r  )*36 + kb + c  ]);
                    aq[fm][1] = __float_as_uint(As[(r+8)*36 + kb + c  ]);
                    aq[fm][2] = __float_as_uint(As[(r  )*36 + kb + c+4]);
                    aq[fm][3] = __float_as_uint(As[(r+8)*36 + kb + c+4]);
                    ak[fm][0] = __float_as_uint(As[(r+1)*36 + kb + c  ]);
                    ak[fm][1] = __float_as_uint(As[(r+9)*36 + kb + c  ]);
                    ak[fm][2] = __float_as_uint(As[(r+1)*36 + kb + c+4]);
                    ak[fm][3] = __float_as_uint(As[(r+9)*36 + kb + c+4]);
                }
                uint32_t bq[8][2], bk[8][2];
#pragma unroll
                for (int fn = 0; fn < 8; ++fn){
                    int e = rn + fn*8 + grp;
                    bq[fn][0] = __float_as_uint(Bs[(e    )*36 + kb + c  ]);
                    bq[fn][1] = __float_as_uint(Bs[(e    )*36 + kb + c+4]);
                    bk[fn][0] = __float_as_uint(Bs[(e+128)*36 + kb + c  ]);
                    bk[fn][1] = __float_as_uint(Bs[(e+128)*36 + kb + c+4]);
                }
#pragma unroll
                for (int fm = 0; fm < 2; ++fm)
#pragma unroll
                    for (int fn = 0; fn < 8; ++fn){
                        mma8(dq[fm][fn], aq[fm], bq[fn]);
                        mma8(dk[fm][fn], ak[fm], bk[fn]);
                    }
            }
            __syncthreads();
        }

        // fold this e-pass into per-row scalars (rows: rm + grp + fm*16 + h*8)
#pragma unroll
        for (int fm = 0; fm < 2; ++fm)
#pragma unroll
            for (int h = 0; h < 2; ++h){
                const int slot = fm*2 + h;
#pragma unroll
                for (int fn = 0; fn < 8; ++fn){
                    float q0 = dq[fm][fn][h*2], q1 = dq[fm][fn][h*2+1];
                    float k0 = dk[fm][fn][h*2], k1 = dk[fm][fn][h*2+1];
                    qq[slot] = fmaf(q0,q0, fmaf(q1,q1, qq[slot]));
                    kk[slot] = fmaf(k0,k0, fmaf(k1,k1, kk[slot]));
                    qk[slot] = fmaf(q0,k0, fmaf(q1,k1, qk[slot]));
                }
            }
    }

    // sum the 4 c-lanes of each quad (same rows, different output columns)
#pragma unroll
    for (int i = 0; i < 4; ++i){
#pragma unroll
        for (int s = 1; s < 4; s <<= 1){
            qq[i] += __shfl_xor_sync(0xffffffffu, qq[i], s);
            kk[i] += __shfl_xor_sync(0xffffffffu, kk[i], s);
            qk[i] += __shfl_xor_sync(0xffffffffu, qk[i], s);
        }
    }
    __syncthreads();
    float* red = dsm;   // 768 floats, pipeline fully drained
    if (c == 0){
#pragma unroll
        for (int slot = 0; slot < 4; ++slot){
            int row = rm + grp + (slot&1)*8 + (slot>>1)*16;
            red[      warp_n*128 + row] = qq[slot];
            red[256 + warp_n*128 + row] = kk[slot];
            red[512 + warp_n*128 + row] = qk[slot];
        }
    }
    __syncthreads();
    if (tid < 128){
        float sqq = red[tid]     + red[128+tid];
        float skk = red[256+tid] + red[384+tid];
        float sqk = red[512+tid] + red[640+tid];
        int t = t0 + tid;
        if (t < LL-1){
            float invnn = 1.f/(fmaxf(sqrtf(sqq),1e-12f)*fmaxf(sqrtf(skk),1e-12f));
            float cosv  = sqk * invnn;
            g_invnn[b*LL + t] = invnn;
            g_prob[b*LL + t + 1] = fminf(fmaxf((1.f - cosv)*0.5f, 0.f), 1.f);
            if (fabsf(cosv) < BANDC){
                int pos = atomicAdd(&g_fcnt, 1);
                if (pos < FCAP) g_flist[pos] = b*LL + t;
            }
        }
        if (t0 == 0 && tid == 0) g_prob[b*LL] = 1.0f;
    }
}

// ---------------- K1b: exact fp32 qk for flagged tokens ----------------
__global__ __launch_bounds__(256)
void k_fix1(const float* __restrict__ hid, const float* __restrict__ wq, const float* __restrict__ wk)
{
    __shared__ float Xa[32][33], Xb[32][33], Wq[128][33], Wk[128][33];
    __shared__ int   sga[32];
    __shared__ float sred[8][32];

    const int cnt = min(g_fcnt, FCAP);
    if ((int)blockIdx.x * 32 >= cnt) return;

    const int tid  = threadIdx.x;
    const int w    = tid >> 5, lane = tid & 31;
    const int tokg = lane & 7, esub = lane >> 3;
    const int tok0 = tokg * 4;
    const int eL   = w*16 + esub*4;
    const int eG   = blockIdx.y*128;

    if (tid < 32){
        int idx = blockIdx.x*32 + tid;
        sga[tid] = g_flist[min(idx, cnt-1)];
    }
    __syncthreads();

    float qe[4][4], ke[4][4];
#pragma unroll
    for (int i=0;i<4;i++)
#pragma unroll
        for (int j=0;j<4;j++){ qe[i][j]=0.f; ke[i][j]=0.f; }

    for (int kc = 0; kc < DD; kc += 32){
        for (int v = tid; v < 1024; v += 256){
            int tk = v >> 5, k = v & 31;
            size_t g = (size_t)sga[tk];
            Xa[tk][k] = hid[g*DD + kc + k];
            Xb[tk][k] = hid[(g+1)*DD + kc + k];
        }
        for (int v = tid; v < 4096; v += 256){
            int e = v >> 5, k = v & 31;
            Wq[e][k] = wq[(size_t)(eG+e)*DD + kc + k];
            Wk[e][k] = wk[(size_t)(eG+e)*DD + kc + k];
        }
        __syncthreads();
#pragma unroll 4
        for (int k = 0; k < 32; ++k){
            float xa0 = Xa[tok0+0][k], xa1 = Xa[tok0+1][k], xa2 = Xa[tok0+2][k], xa3 = Xa[tok0+3][k];
            float xb0 = Xb[tok0+0][k], xb1 = Xb[tok0+1][k], xb2 = Xb[tok0+2][k], xb3 = Xb[tok0+3][k];
#pragma unroll
            for (int j = 0; j < 4; ++j){
                float wqv = Wq[eL+j][k], wkv = Wk[eL+j][k];
                qe[0][j] = fmaf(wqv, xa0, qe[0][j]);
                qe[1][j] = fmaf(wqv, xa1, qe[1][j]);
                qe[2][j] = fmaf(wqv, xa2, qe[2][j]);
                qe[3][j] = fmaf(wqv, xa3, qe[3][j]);
                ke[0][j] = fmaf(wkv, xb0, ke[0][j]);
                ke[1][j] = fmaf(wkv, xb1, ke[1][j]);
                ke[2][j] = fmaf(wkv, xb2, ke[2][j]);
                ke[3][j] = fmaf(wkv, xb3, ke[3][j]);
            }
        }
        __syncthreads();
    }

    float p[4];
#pragma unroll
    for (int i=0;i<4;i++){
        p[i] = 0.f;
#pragma unroll
        for (int j=0;j<4;j++) p[i] = fmaf(qe[i][j], ke[i][j], p[i]);
#pragma unroll
        for (int s = 8; s < 32; s <<= 1)
            p[i] += __shfl_xor_sync(0xffffffffu, p[i], s);
    }
    if (esub == 0){
#pragma unroll
        for (int i=0;i<4;i++) sred[w][tok0+i] = p[i];
    }
    __syncthreads();
    if (tid < 32){
        float s = 0.f;
#pragma unroll
        for (int ww=0; ww<8; ww++) s += sred[ww][tid];
        g_qkpart[(blockIdx.x*32 + tid)*8 + blockIdx.y] = s;
    }
}

__global__ __launch_bounds__(256)
void k_fix2()
{
    const int cnt = min(g_fcnt, FCAP);
    int i = blockIdx.x*256 + threadIdx.x;
    if (i >= cnt) return;
    float qk = 0.f;
#pragma unroll
    for (int y = 0; y < 8; ++y) qk += g_qkpart[i*8 + y];
    int g = g_flist[i];
    float cosv = qk * g_invnn[g];
    g_prob[g + 1] = fminf(fmaxf((1.f - cosv)*0.5f, 0.f), 1.f);
}

// ---------------- K2: mask scan / compaction ----------------
__global__ __launch_bounds__(1024)
void k_scan()
{
    const int b = blockIdx.x;
    const int tid = threadIdx.x;
    __shared__ int wsum[32];

    const int base = b*LL + tid*4;
    float p[4]; int m[4]; int s = 0;
#pragma unroll
    for (int i=0;i<4;i++){
        p[i] = g_prob[base+i];
        m[i] = p[i] > 0.5f ? 1 : 0;
        s += m[i];
    }
    const int lane = tid & 31, wid = tid >> 5;
    int incl = s;
#pragma unroll
    for (int o=1;o<32;o<<=1){
        int v = __shfl_up_sync(0xffffffffu, incl, o);
        if (lane >= o) incl += v;
    }
    if (lane == 31) wsum[wid] = incl;
    __syncthreads();
    if (tid < 32) {
        int v = wsum[tid];
        int iv = v;
#pragma unroll
        for (int o=1;o<32;o<<=1){
            int u = __shfl_up_sync(0xffffffffu, iv, o);
            if (tid >= o) iv += u;
        }
        wsum[tid] = iv - v;
    }
    __syncthreads();
    int run = incl - s + wsum[wid];
#pragma unroll
    for (int i=0;i<4;i++){
        if (m[i]) {
            g_src[b*LL + run]   = tid*4 + i;
            g_decay[b*LL + run] = fminf(fmaxf(1.f - p[i], 0.f), 1.f);
            run++;
        }
        g_cidx[base + i] = run - 1;
    }
    if (tid == 1023) g_counts[b] = run;
}

// ---------------- K3: EMA recurrence over chunks ----------------
__global__ __launch_bounds__(128)
void k_ema(const float* __restrict__ hid, const float* __restrict__ init)
{
    const int b = blockIdx.y;
    const int d = blockIdx.x * 128 + threadIdx.x;
    const float* hb = hid + (size_t)b*LL*DD;
    float state = init[b*DD + d];
    const int n = g_counts[b];
    const int*   src = g_src   + b*LL;
    const float* dec = g_decay + b*LL;
    float* emab = g_ema + (size_t)b*LL*DD;
    for (int j = 0; j < n; ++j) {
        int   t = __ldg(src + j);
        float a = __ldg(dec + j);
        float x = __ldg(hb + (size_t)t*DD + d);
        state = a*state + (1.f - a)*x;
        emab[(size_t)j*DD + d] = state;
    }
}

// ---------------- K4: broadcast back + residual ----------------
__global__ __launch_bounds__(256)
void k_out(const float* __restrict__ res, float* __restrict__ out)
{
    size_t gid  = (size_t)blockIdx.x * 256 + threadIdx.x;
    size_t flat = gid * 4;
    int d = (int)(flat & (DD-1));
    int t = (int)((flat >> 10) & (LL-1));
    int b = (int)(flat >> 22);
    int ci = g_cidx[b*LL + t];
    float4 r = *(const float4*)(res + flat);
    float4 e = *(const float4*)(g_ema + ((size_t)(b*LL + ci))*DD + d);
    float4 o = make_float4(r.x+e.x, r.y+e.y, r.z+e.z, r.w+e.w);
    *(float4*)(out + flat) = o;
}

// ---------------- launch ----------------
extern "C" void kernel_launch(void* const* d_in, const int* in_sizes, int n_in,
                              void* d_out, int out_size)
{
    const float* hid = (const float*)d_in[0];
    const float* res = (const float*)d_in[1];
    const float* wq  = (const float*)d_in[2];
    const float* wk  = (const float*)d_in[3];
    const float* ini = (const float*)d_in[4];
    float* out = (float*)d_out;

    float *xr, *wqr, *wkr;
    cudaGetSymbolAddress((void**)&xr,  g_xr);
    cudaGetSymbolAddress((void**)&wqr, g_wqr);
    cudaGetSymbolAddress((void**)&wkr, g_wkr);

    cudaFuncSetAttribute(k_rmma, cudaFuncAttributeMaxDynamicSharedMemorySize, RSMEM);

    const int nh4 = BB*LL*DD/4, nw4 = DD*DD/4;
    k_zero <<<1, 1>>>();
    k_round<<<(nh4+255)/256, 256>>>(hid, xr, nh4);
    k_round<<<(nw4+255)/256, 256>>>(wq, wqr, nw4);
    k_round<<<(nw4+255)/256, 256>>>(wk, wkr, nw4);

    k_rmma<<<dim3(32, BB), 256, RSMEM>>>();
    k_fix1<<<dim3(FCAP/32, 8), 256>>>(hid, wq, wk);
    k_fix2<<<(FCAP+255)/256, 256>>>();

    k_scan<<<BB, 1024>>>();
    k_ema <<<dim3(DD/128, BB), 128>>>(hid, ini);
    k_out <<<(BB*LL*DD/4 + 255)/256, 256>>>(res, out);
}

// round 12
// speedup vs baseline: 1.8583x; 1.0349x over previous
#include <cuda_runtime.h>
#include <cstdint>

#define BB 4
#define LL 4096
#define DD 1024
#define HT (BB*LL)
#define FCAP 4096
#define BANDC 5e-4f

// ---------------- scratch (static device globals; zero-initialized) ----------------
__device__ float g_prob[BB*LL];
__device__ float g_invnn[BB*LL];
__device__ float g_decay[BB*LL];
__device__ int   g_src[BB*LL];
__device__ int   g_cidx[BB*LL];
__device__ int   g_counts[BB];
__device__ int   g_fcnt;
__device__ int   g_flist[FCAP];
__device__ float g_qkpart[FCAP*8];
__device__ float g_ema[(size_t)BB*LL*DD];      // 64 MB
__device__ float g_xr[(size_t)(HT+136)*DD];    // rounded X; rows >= HT stay zero
__device__ float g_wqr[(size_t)DD*DD];
__device__ float g_wkr[(size_t)DD*DD];

// ---------------- helpers ----------------
__device__ __forceinline__ float tf32r(float x){
    uint32_t u; asm("cvt.rna.tf32.f32 %0, %1;" : "=r"(u) : "f"(x));
    return __uint_as_float(u);
}
__device__ __forceinline__ void cpa16s(uint32_t daddr, const float* src){
    asm volatile("cp.async.cg.shared.global [%0], [%1], 16;" :: "r"(daddr), "l"(src));
}
__device__ __forceinline__ void mma8(float* d, const uint32_t* a, const uint32_t* b){
    asm("mma.sync.aligned.m16n8k8.row.col.f32.tf32.tf32.f32 "
        "{%0,%1,%2,%3}, {%4,%5,%6,%7}, {%8,%9}, {%0,%1,%2,%3};"
        : "+f"(d[0]), "+f"(d[1]), "+f"(d[2]), "+f"(d[3])
        : "r"(a[0]), "r"(a[1]), "r"(a[2]), "r"(a[3]), "r"(b[0]), "r"(b[1]));
}
__device__ __forceinline__ void ldm4(uint32_t* r, uint32_t saddr){
    asm volatile("ldmatrix.sync.aligned.m8n8.x4.shared.b16 {%0,%1,%2,%3}, [%4];"
        : "=r"(r[0]), "=r"(r[1]), "=r"(r[2]), "=r"(r[3]) : "r"(saddr));
}

// ---------------- K0: round fp32 -> tf32(RNA) ----------------
__global__ __launch_bounds__(256)
void k_round(const float* __restrict__ in, float* __restrict__ out, int n4)
{
    int i = blockIdx.x*256 + threadIdx.x;
    if (i >= n4) return;
    float4 x = ((const float4*)in)[i];
    float4 h;
    h.x = tf32r(x.x); h.y = tf32r(x.y); h.z = tf32r(x.z); h.w = tf32r(x.w);
    ((float4*)out)[i] = h;
}
__global__ void k_zero(){ g_fcnt = 0; }

// ---------------- K1: HMMA tf32 router (ldmatrix + 3-stage cp.async) ----------------
// stage: A 129 rows (pad 132) x 32k, stride 36 ; B 256 rows x 32k, stride 36
#define ASZ_FL (132*36)                 // 4752 floats
#define STG_FL (ASZ_FL + 256*36)        // 13968 floats
#define STG_B  (STG_FL*4)               // 55872 bytes
#define RSMEM  (3*STG_B)                // 167616 bytes

__device__ __forceinline__ void ld_stage(uint32_t sbb, size_t arow0, int e0, int kc, int tid)
{
    for (int v = tid; v < 3080; v += 256){
        const float* src;
        uint32_t dst;
        if (v < 1032){                       // A: 129 rows x 8 float4
            int row = v >> 3, kg = v & 7;
            src = g_xr + (arow0 + (size_t)row)*DD + kc + kg*4;
            dst = (uint32_t)(row*144 + kg*16);
        } else {                             // B: 256 rows x 8 float4
            int u = v - 1032;
            int row = u >> 3, kg = u & 7;
            const float* w = (row < 128) ? g_wqr : g_wkr;
            src = w + (size_t)(e0 + (row & 127))*DD + kc + kg*4;
            dst = (uint32_t)(ASZ_FL*4 + row*144 + kg*16);
        }
        cpa16s(sbb + dst, src);
    }
}

extern __shared__ float dsm[];

__global__ __launch_bounds__(256, 1)
void k_rmma()
{
    const int b   = blockIdx.y;
    const int t0  = blockIdx.x * 128;
    const int tid = threadIdx.x;
    const int wid = tid >> 5, lane = tid & 31;
    const int warp_m = wid & 3, warp_n = wid >> 2;
    const int rm = warp_m*32, rn = warp_n*64;
    const int grp = lane >> 2, c = lane & 3;
    const size_t arow0 = (size_t)b*LL + t0;
    const uint32_t sbb = (uint32_t)__cvta_generic_to_shared(dsm);

    // ldmatrix per-lane source offsets (bytes, stage-relative)
    const int tile  = lane >> 3;         // 0..3
    const int rowin = lane & 7;
    uint32_t offAq[2], offAk[2], offBq[4], offBk[4];
#pragma unroll
    for (int fm = 0; fm < 2; ++fm){
        int r = rm + fm*16 + rowin + (tile & 1)*8;
        offAq[fm] = (uint32_t)(r*144 + (tile >> 1)*16);
        offAk[fm] = offAq[fm] + 144;
    }
#pragma unroll
    for (int p = 0; p < 4; ++p){
        int e = rn + (2*p + (tile >> 1))*8 + rowin;
        offBq[p] = (uint32_t)(ASZ_FL*4 + e*144 + (tile & 1)*16);
        offBk[p] = offBq[p] + 128*144;
    }

    float qq[4], kk[4], qk[4];
#pragma unroll
    for (int i=0;i<4;i++){ qq[i]=0.f; kk[i]=0.f; qk[i]=0.f; }

    for (int ep = 0; ep < 8; ++ep){
        const int e0 = ep*128;
        float dq[2][8][4], dk[2][8][4];
#pragma unroll
        for (int fm=0; fm<2; fm++)
#pragma unroll
            for (int fn=0; fn<8; fn++)
#pragma unroll
                for (int r=0; r<4; r++){ dq[fm][fn][r]=0.f; dk[fm][fn][r]=0.f; }

        ld_stage(sbb,         arow0, e0,  0, tid);
        asm volatile("cp.async.commit_group;" ::: "memory");
        ld_stage(sbb + STG_B, arow0, e0, 32, tid);
        asm volatile("cp.async.commit_group;" ::: "memory");

        for (int ch = 0; ch < 32; ++ch){
            if (ch < 31) asm volatile("cp.async.wait_group 1;" ::: "memory");
            else         asm volatile("cp.async.wait_group 0;" ::: "memory");
            __syncthreads();

            if (ch + 2 < 32){
                ld_stage(sbb + (uint32_t)(((ch+2)%3)*STG_B), arow0, e0, (ch+2)*32, tid);
                asm volatile("cp.async.commit_group;" ::: "memory");
            }

            const uint32_t sb = sbb + (uint32_t)((ch%3)*STG_B);

#pragma unroll
            for (int k8 = 0; k8 < 4; ++k8){
                const uint32_t kbB = (uint32_t)(k8*32);
                uint32_t aq[2][4], ak[2][4], bq[4][4], bk[4][4];
                ldm4(aq[0], sb + offAq[0] + kbB);
                ldm4(aq[1], sb + offAq[1] + kbB);
                ldm4(ak[0], sb + offAk[0] + kbB);
                ldm4(ak[1], sb + offAk[1] + kbB);
#pragma unroll
                for (int p = 0; p < 4; ++p){
                    ldm4(bq[p], sb + offBq[p] + kbB);
                    ldm4(bk[p], sb + offBk[p] + kbB);
                }
#pragma unroll
                for (int fm = 0; fm < 2; ++fm)
#pragma unroll
                    for (int fn = 0; fn < 8; ++fn){
                        mma8(dq[fm][fn], aq[fm], &bq[fn>>1][(fn&1)*2]);
                        mma8(dk[fm][fn], ak[fm], &bk[fn>>1][(fn&1)*2]);
                    }
            }
        }
        __syncthreads();

        // fold this e-pass into per-row scalars (rows: rm + grp + fm*16 + h*8)
#pragma unroll
        for (int fm = 0; fm < 2; ++fm)
#pragma unroll
            for (int h = 0; h < 2; ++h){
                const int slot = fm*2 + h;
#pragma unroll
                for (int fn = 0; fn < 8; ++fn){
                    float q0 = dq[fm][fn][h*2], q1 = dq[fm][fn][h*2+1];
                    float k0 = dk[fm][fn][h*2], k1 = dk[fm][fn][h*2+1];
                    qq[slot] = fmaf(q0,q0, fmaf(q1,q1, qq[slot]));
                    kk[slot] = fmaf(k0,k0, fmaf(k1,k1, kk[slot]));
                    qk[slot] = fmaf(q0,k0, fmaf(q1,k1, qk[slot]));
                }
            }
    }

    // sum the 4 c-lanes of each quad (same rows, different output columns)
#pragma unroll
    for (int i = 0; i < 4; ++i){
#pragma unroll
        for (int s = 1; s < 4; s <<= 1){
            qq[i] += __shfl_xor_sync(0xffffffffu, qq[i], s);
            kk[i] += __shfl_xor_sync(0xffffffffu, kk[i], s);
            qk[i] += __shfl_xor_sync(0xffffffffu, qk[i], s);
        }
    }
    __syncthreads();
    float* red = dsm;   // 768 floats; pipeline fully drained
    if (c == 0){
#pragma unroll
        for (int slot = 0; slot < 4; ++slot){
            int row = rm + grp + (slot&1)*8 + (slot>>1)*16;
            red[      warp_n*128 + row] = qq[slot];
            red[256 + warp_n*128 + row] = kk[slot];
            red[512 + warp_n*128 + row] = qk[slot];
        }
    }
    __syncthreads();
    if (tid < 128){
        float sqq = red[tid]     + red[128+tid];
        float skk = red[256+tid] + red[384+tid];
        float sqk = red[512+tid] + red[640+tid];
        int t = t0 + tid;
        if (t < LL-1){
            float invnn = 1.f/(fmaxf(sqrtf(sqq),1e-12f)*fmaxf(sqrtf(skk),1e-12f));
            float cosv  = sqk * invnn;
            g_invnn[b*LL + t] = invnn;
            g_prob[b*LL + t + 1] = fminf(fmaxf((1.f - cosv)*0.5f, 0.f), 1.f);
            if (fabsf(cosv) < BANDC){
                int pos = atomicAdd(&g_fcnt, 1);
                if (pos < FCAP) g_flist[pos] = b*LL + t;
            }
        }
        if (t0 == 0 && tid == 0) g_prob[b*LL] = 1.0f;
    }
}

// ---------------- K1b: exact fp32 qk for flagged tokens ----------------
__global__ __launch_bounds__(256)
void k_fix1(const float* __restrict__ hid, const float* __restrict__ wq, const float* __restrict__ wk)
{
    __shared__ float Xa[32][33], Xb[32][33], Wq[128][33], Wk[128][33];
    __shared__ int   sga[32];
    __shared__ float sred[8][32];

    const int cnt = min(g_fcnt, FCAP);
    if ((int)blockIdx.x * 32 >= cnt) return;

    const int tid  = threadIdx.x;
    const int w    = tid >> 5, lane = tid & 31;
    const int tokg = lane & 7, esub = lane >> 3;
    const int tok0 = tokg * 4;
    const int eL   = w*16 + esub*4;
    const int eG   = blockIdx.y*128;

    if (tid < 32){
        int idx = blockIdx.x*32 + tid;
        sga[tid] = g_flist[min(idx, cnt-1)];
    }
    __syncthreads();

    float qe[4][4], ke[4][4];
#pragma unroll
    for (int i=0;i<4;i++)
#pragma unroll
        for (int j=0;j<4;j++){ qe[i][j]=0.f; ke[i][j]=0.f; }

    for (int kc = 0; kc < DD; kc += 32){
        for (int v = tid; v < 1024; v += 256){
            int tk = v >> 5, k = v & 31;
            size_t g = (size_t)sga[tk];
            Xa[tk][k] = hid[g*DD + kc + k];
            Xb[tk][k] = hid[(g+1)*DD + kc + k];
        }
        for (int v = tid; v < 4096; v += 256){
            int e = v >> 5, k = v & 31;
            Wq[e][k] = wq[(size_t)(eG+e)*DD + kc + k];
            Wk[e][k] = wk[(size_t)(eG+e)*DD + kc + k];
        }
        __syncthreads();
#pragma unroll 4
        for (int k = 0; k < 32; ++k){
            float xa0 = Xa[tok0+0][k], xa1 = Xa[tok0+1][k], xa2 = Xa[tok0+2][k], xa3 = Xa[tok0+3][k];
            float xb0 = Xb[tok0+0][k], xb1 = Xb[tok0+1][k], xb2 = Xb[tok0+2][k], xb3 = Xb[tok0+3][k];
#pragma unroll
            for (int j = 0; j < 4; ++j){
                float wqv = Wq[eL+j][k], wkv = Wk[eL+j][k];
                qe[0][j] = fmaf(wqv, xa0, qe[0][j]);
                qe[1][j] = fmaf(wqv, xa1, qe[1][j]);
                qe[2][j] = fmaf(wqv, xa2, qe[2][j]);
                qe[3][j] = fmaf(wqv, xa3, qe[3][j]);
                ke[0][j] = fmaf(wkv, xb0, ke[0][j]);
                ke[1][j] = fmaf(wkv, xb1, ke[1][j]);
                ke[2][j] = fmaf(wkv, xb2, ke[2][j]);
                ke[3][j] = fmaf(wkv, xb3, ke[3][j]);
            }
        }
        __syncthreads();
    }

    float p[4];
#pragma unroll
    for (int i=0;i<4;i++){
        p[i] = 0.f;
#pragma unroll
        for (int j=0;j<4;j++) p[i] = fmaf(qe[i][j], ke[i][j], p[i]);
#pragma unroll
        for (int s = 8; s < 32; s <<= 1)
            p[i] += __shfl_xor_sync(0xffffffffu, p[i], s);
    }
    if (esub == 0){
#pragma unroll
        for (int i=0;i<4;i++) sred[w][tok0+i] = p[i];
    }
    __syncthreads();
    if (tid < 32){
        float s = 0.f;
#pragma unroll
        for (int ww=0; ww<8; ww++) s += sred[ww][tid];
        g_qkpart[(blockIdx.x*32 + tid)*8 + blockIdx.y] = s;
    }
}

__global__ __launch_bounds__(256)
void k_fix2()
{
    const int cnt = min(g_fcnt, FCAP);
    int i = blockIdx.x*256 + threadIdx.x;
    if (i >= cnt) return;
    float qk = 0.f;
#pragma unroll
    for (int y = 0; y < 8; ++y) qk += g_qkpart[i*8 + y];
    int g = g_flist[i];
    float cosv = qk * g_invnn[g];
    g_prob[g + 1] = fminf(fmaxf((1.f - cosv)*0.5f, 0.f), 1.f);
}

// ---------------- K2: mask scan / compaction ----------------
__global__ __launch_bounds__(1024)
void k_scan()
{
    const int b = blockIdx.x;
    const int tid = threadIdx.x;
    __shared__ int wsum[32];

    const int base = b*LL + tid*4;
    float p[4]; int m[4]; int s = 0;
#pragma unroll
    for (int i=0;i<4;i++){
        p[i] = g_prob[base+i];
        m[i] = p[i] > 0.5f ? 1 : 0;
        s += m[i];
    }
    const int lane = tid & 31, wid = tid >> 5;
    int incl = s;
#pragma unroll
    for (int o=1;o<32;o<<=1){
        int v = __shfl_up_sync(0xffffffffu, incl, o);
        if (lane >= o) incl += v;
    }
    if (lane == 31) wsum[wid] = incl;
    __syncthreads();
    if (tid < 32) {
        int v = wsum[tid];
        int iv = v;
#pragma unroll
        for (int o=1;o<32;o<<=1){
            int u = __shfl_up_sync(0xffffffffu, iv, o);
            if (tid >= o) iv += u;
        }
        wsum[tid] = iv - v;
    }
    __syncthreads();
    int run = incl - s + wsum[wid];
#pragma unroll
    for (int i=0;i<4;i++){
        if (m[i]) {
            g_src[b*LL + run]   = tid*4 + i;
            g_decay[b*LL + run] = fminf(fmaxf(1.f - p[i], 0.f), 1.f);
            run++;
        }
        g_cidx[base + i] = run - 1;
    }
    if (tid == 1023) g_counts[b] = run;
}

// ---------------- K3: EMA recurrence over chunks ----------------
__global__ __launch_bounds__(128)
void k_ema(const float* __restrict__ hid, const float* __restrict__ init)
{
    const int b = blockIdx.y;
    const int d = blockIdx.x * 128 + threadIdx.x;
    const float* hb = hid + (size_t)b*LL*DD;
    float state = init[b*DD + d];
    const int n = g_counts[b];
    const int*   src = g_src   + b*LL;
    const float* dec = g_decay + b*LL;
    float* emab = g_ema + (size_t)b*LL*DD;
    for (int j = 0; j < n; ++j) {
        int   t = __ldg(src + j);
        float a = __ldg(dec + j);
        float x = __ldg(hb + (size_t)t*DD + d);
        state = a*state + (1.f - a)*x;
        emab[(size_t)j*DD + d] = state;
    }
}

// ---------------- K4: broadcast back + residual ----------------
__global__ __launch_bounds__(256)
void k_out(const float* __restrict__ res, float* __restrict__ out)
{
    size_t gid  = (size_t)blockIdx.x * 256 + threadIdx.x;
    size_t flat = gid * 4;
    int d = (int)(flat & (DD-1));
    int t = (int)((flat >> 10) & (LL-1));
    int b = (int)(flat >> 22);
    int ci = g_cidx[b*LL + t];
    float4 r = *(const float4*)(res + flat);
    float4 e = *(const float4*)(g_ema + ((size_t)(b*LL + ci))*DD + d);
    float4 o = make_float4(r.x+e.x, r.y+e.y, r.z+e.z, r.w+e.w);
    *(float4*)(out + flat) = o;
}

// ---------------- launch ----------------
extern "C" void kernel_launch(void* const* d_in, const int* in_sizes, int n_in,
                              void* d_out, int out_size)
{
    const float* hid = (const float*)d_in[0];
    const float* res = (const float*)d_in[1];
    const float* wq  = (const float*)d_in[2];
    const float* wk  = (const float*)d_in[3];
    const float* ini = (const float*)d_in[4];
    float* out = (float*)d_out;

    float *xr, *wqr, *wkr;
    cudaGetSymbolAddress((void**)&xr,  g_xr);
    cudaGetSymbolAddress((void**)&wqr, g_wqr);
    cudaGetSymbolAddress((void**)&wkr, g_wkr);

    cudaFuncSetAttribute(k_rmma, cudaFuncAttributeMaxDynamicSharedMemorySize, RSMEM);

    const int nh4 = BB*LL*DD/4, nw4 = DD*DD/4;
    k_zero <<<1, 1>>>();
    k_round<<<(nh4+255)/256, 256>>>(hid, xr, nh4);
    k_round<<<(nw4+255)/256, 256>>>(wq, wqr, nw4);
    k_round<<<(nw4+255)/256, 256>>>(wk, wkr, nw4);

    k_rmma<<<dim3(32, BB), 256, RSMEM>>>();
    k_fix1<<<dim3(FCAP/32, 8), 256>>>(hid, wq, wk);
    k_fix2<<<(FCAP+255)/256, 256>>>();

    k_scan<<<BB, 1024>>>();
    k_ema <<<dim3(DD/128, BB), 128>>>(hid, ini);
    k_out <<<(BB*LL*DD/4 + 255)/256, 256>>>(res, out);
}

// round 13
// speedup vs baseline: 1.9102x; 1.0279x over previous
#include <cuda_runtime.h>
#include <cstdint>

#define BB 4
#define LL 4096
#define DD 1024
#define HT (BB*LL)
#define FCAP 4096
#define BANDC 5e-4f

// ---------------- scratch (static device globals; zero-initialized) ----------------
__device__ float g_prob[BB*LL];
__device__ float g_invnn[BB*LL];
__device__ float g_decay[BB*LL];
__device__ int   g_src[BB*LL];
__device__ int   g_cidx[BB*LL];
__device__ int   g_counts[BB];
__device__ int   g_fcnt;
__device__ int   g_flist[FCAP];
__device__ float g_qkpart[FCAP*8];
__device__ float g_ema[(size_t)BB*LL*DD];      // 64 MB
__device__ float g_xr[(size_t)(HT+136)*DD];    // rounded X; rows >= HT stay zero
__device__ float g_wqr[(size_t)DD*DD];
__device__ float g_wkr[(size_t)DD*DD];

// ---------------- helpers ----------------
__device__ __forceinline__ float tf32r(float x){
    uint32_t u; asm("cvt.rna.tf32.f32 %0, %1;" : "=r"(u) : "f"(x));
    return __uint_as_float(u);
}
__device__ __forceinline__ void cpa16s(uint32_t daddr, const float* src){
    asm volatile("cp.async.cg.shared.global [%0], [%1], 16;" :: "r"(daddr), "l"(src));
}
__device__ __forceinline__ void mma8(float* d, const uint32_t* a, const uint32_t* b){
    asm("mma.sync.aligned.m16n8k8.row.col.f32.tf32.tf32.f32 "
        "{%0,%1,%2,%3}, {%4,%5,%6,%7}, {%8,%9}, {%0,%1,%2,%3};"
        : "+f"(d[0]), "+f"(d[1]), "+f"(d[2]), "+f"(d[3])
        : "r"(a[0]), "r"(a[1]), "r"(a[2]), "r"(a[3]), "r"(b[0]), "r"(b[1]));
}
__device__ __forceinline__ void ldm4(uint32_t* r, uint32_t saddr){
    asm volatile("ldmatrix.sync.aligned.m8n8.x4.shared.b16 {%0,%1,%2,%3}, [%4];"
        : "=r"(r[0]), "=r"(r[1]), "=r"(r[2]), "=r"(r[3]) : "r"(saddr));
}

// ---------------- K0: round fp32 -> tf32(RNA) ----------------
__global__ __launch_bounds__(256)
void k_round(const float* __restrict__ in, float* __restrict__ out, int n4)
{
    int i = blockIdx.x*256 + threadIdx.x;
    if (i >= n4) return;
    float4 x = ((const float4*)in)[i];
    float4 h;
    h.x = tf32r(x.x); h.y = tf32r(x.y); h.z = tf32r(x.z); h.w = tf32r(x.w);
    ((float4*)out)[i] = h;
}
__global__ void k_zero(){ g_fcnt = 0; }

// ---------------- K1: HMMA tf32 router (512 threads, ldmatrix, 3-stage) ----------------
// stage: A 129 rows (pad 132) x 32k, stride 36 fl ; B 256 rows x 32k, stride 36 fl
#define ASZ_FL (132*36)                 // 4752 floats
#define STG_FL (ASZ_FL + 256*36)        // 13968 floats
#define STG_B  (STG_FL*4)               // 55872 bytes
#define RSMEM  (3*STG_B)                // 167616 bytes
#define NT 512

__device__ __forceinline__ void ld_stage(uint32_t sbb, size_t arow0, int e0, int kc, int tid)
{
    for (int v = tid; v < 3080; v += NT){
        const float* src;
        uint32_t dst;
        if (v < 1032){                       // A: 129 rows x 8 float4
            int row = v >> 3, kg = v & 7;
            src = g_xr + (arow0 + (size_t)row)*DD + kc + kg*4;
            dst = (uint32_t)(row*144 + kg*16);
        } else {                             // B: 256 rows x 8 float4
            int u = v - 1032;
            int row = u >> 3, kg = u & 7;
            const float* w = (row < 128) ? g_wqr : g_wkr;
            src = w + (size_t)(e0 + (row & 127))*DD + kc + kg*4;
            dst = (uint32_t)(ASZ_FL*4 + row*144 + kg*16);
        }
        cpa16s(sbb + dst, src);
    }
}

extern __shared__ float dsm[];

__global__ __launch_bounds__(NT, 1)
void k_rmma()
{
    const int b   = blockIdx.y;
    const int t0  = blockIdx.x * 128;
    const int tid = threadIdx.x;
    const int wid = tid >> 5, lane = tid & 31;
    const int warp_m = wid & 3, warp_n = wid >> 2;   // 4 x 4 warp grid
    const int rm = warp_m*32, rn = warp_n*32;
    const int grp = lane >> 2, c = lane & 3;
    const size_t arow0 = (size_t)b*LL + t0;
    const uint32_t sbb = (uint32_t)__cvta_generic_to_shared(dsm);

    // ldmatrix per-lane source offsets (bytes, stage-relative)
    const int tile  = lane >> 3;         // 0..3
    const int rowin = lane & 7;
    uint32_t offAq[2], offAk[2], offBq[2], offBk[2];
#pragma unroll
    for (int fm = 0; fm < 2; ++fm){
        int r = rm + fm*16 + rowin + (tile & 1)*8;
        offAq[fm] = (uint32_t)(r*144 + (tile >> 1)*16);
        offAk[fm] = offAq[fm] + 144;
    }
#pragma unroll
    for (int p = 0; p < 2; ++p){
        int e = rn + (2*p + (tile >> 1))*8 + rowin;
        offBq[p] = (uint32_t)(ASZ_FL*4 + e*144 + (tile & 1)*16);
        offBk[p] = offBq[p] + 128*144;
    }

    float qq[4], kk[4], qk[4];
#pragma unroll
    for (int i=0;i<4;i++){ qq[i]=0.f; kk[i]=0.f; qk[i]=0.f; }

    for (int ep = 0; ep < 8; ++ep){
        const int e0 = ep*128;
        float dq[2][4][4], dk[2][4][4];
#pragma unroll
        for (int fm=0; fm<2; fm++)
#pragma unroll
            for (int fn=0; fn<4; fn++)
#pragma unroll
                for (int r=0; r<4; r++){ dq[fm][fn][r]=0.f; dk[fm][fn][r]=0.f; }

        ld_stage(sbb,         arow0, e0,  0, tid);
        asm volatile("cp.async.commit_group;" ::: "memory");
        ld_stage(sbb + STG_B, arow0, e0, 32, tid);
        asm volatile("cp.async.commit_group;" ::: "memory");

        for (int ch = 0; ch < 32; ++ch){
            if (ch < 31) asm volatile("cp.async.wait_group 1;" ::: "memory");
            else         asm volatile("cp.async.wait_group 0;" ::: "memory");
            __syncthreads();

            if (ch + 2 < 32){
                ld_stage(sbb + (uint32_t)(((ch+2)%3)*STG_B), arow0, e0, (ch+2)*32, tid);
                asm volatile("cp.async.commit_group;" ::: "memory");
            }

            const uint32_t sb = sbb + (uint32_t)((ch%3)*STG_B);

#pragma unroll
            for (int k8 = 0; k8 < 4; ++k8){
                const uint32_t kbB = (uint32_t)(k8*32);
                uint32_t aq[2][4], ak[2][4], bq[2][4], bk[2][4];
                ldm4(aq[0], sb + offAq[0] + kbB);
                ldm4(aq[1], sb + offAq[1] + kbB);
                ldm4(ak[0], sb + offAk[0] + kbB);
                ldm4(ak[1], sb + offAk[1] + kbB);
                ldm4(bq[0], sb + offBq[0] + kbB);
                ldm4(bq[1], sb + offBq[1] + kbB);
                ldm4(bk[0], sb + offBk[0] + kbB);
                ldm4(bk[1], sb + offBk[1] + kbB);
#pragma unroll
                for (int fm = 0; fm < 2; ++fm)
#pragma unroll
                    for (int fn = 0; fn < 4; ++fn){
                        mma8(dq[fm][fn], aq[fm], &bq[fn>>1][(fn&1)*2]);
                        mma8(dk[fm][fn], ak[fm], &bk[fn>>1][(fn&1)*2]);
                    }
            }
        }
        __syncthreads();

        // fold this e-pass into per-row scalars (rows: rm + grp + fm*16 + h*8)
#pragma unroll
        for (int fm = 0; fm < 2; ++fm)
#pragma unroll
            for (int h = 0; h < 2; ++h){
                const int slot = fm*2 + h;
#pragma unroll
                for (int fn = 0; fn < 4; ++fn){
                    float q0 = dq[fm][fn][h*2], q1 = dq[fm][fn][h*2+1];
                    float k0 = dk[fm][fn][h*2], k1 = dk[fm][fn][h*2+1];
                    qq[slot] = fmaf(q0,q0, fmaf(q1,q1, qq[slot]));
                    kk[slot] = fmaf(k0,k0, fmaf(k1,k1, kk[slot]));
                    qk[slot] = fmaf(q0,k0, fmaf(q1,k1, qk[slot]));
                }
            }
    }

    // sum the 4 c-lanes of each quad (same rows, different output columns)
#pragma unroll
    for (int i = 0; i < 4; ++i){
#pragma unroll
        for (int s = 1; s < 4; s <<= 1){
            qq[i] += __shfl_xor_sync(0xffffffffu, qq[i], s);
            kk[i] += __shfl_xor_sync(0xffffffffu, kk[i], s);
            qk[i] += __shfl_xor_sync(0xffffffffu, qk[i], s);
        }
    }
    __syncthreads();
    float* red = dsm;   // 3 x 4 x 128 floats; pipeline fully drained
    if (c == 0){
#pragma unroll
        for (int slot = 0; slot < 4; ++slot){
            int row = rm + grp + (slot&1)*8 + (slot>>1)*16;
            red[       warp_n*128 + row] = qq[slot];
            red[512  + warp_n*128 + row] = kk[slot];
            red[1024 + warp_n*128 + row] = qk[slot];
        }
    }
    __syncthreads();
    if (tid < 128){
        float sqq = red[tid]      + red[128+tid]  + red[256+tid]  + red[384+tid];
        float skk = red[512+tid]  + red[640+tid]  + red[768+tid]  + red[896+tid];
        float sqk = red[1024+tid] + red[1152+tid] + red[1280+tid] + red[1408+tid];
        int t = t0 + tid;
        if (t < LL-1){
            float invnn = 1.f/(fmaxf(sqrtf(sqq),1e-12f)*fmaxf(sqrtf(skk),1e-12f));
            float cosv  = sqk * invnn;
            g_invnn[b*LL + t] = invnn;
            g_prob[b*LL + t + 1] = fminf(fmaxf((1.f - cosv)*0.5f, 0.f), 1.f);
            if (fabsf(cosv) < BANDC){
                int pos = atomicAdd(&g_fcnt, 1);
                if (pos < FCAP) g_flist[pos] = b*LL + t;
            }
        }
        if (t0 == 0 && tid == 0) g_prob[b*LL] = 1.0f;
    }
}

// ---------------- K1b: exact fp32 qk for flagged tokens ----------------
__global__ __launch_bounds__(256)
void k_fix1(const float* __restrict__ hid, const float* __restrict__ wq, const float* __restrict__ wk)
{
    __shared__ float Xa[32][33], Xb[32][33], Wq[128][33], Wk[128][33];
    __shared__ int   sga[32];
    __shared__ float sred[8][32];

    const int cnt = min(g_fcnt, FCAP);
    if ((int)blockIdx.x * 32 >= cnt) return;

    const int tid  = threadIdx.x;
    const int w    = tid >> 5, lane = tid & 31;
    const int tokg = lane & 7, esub = lane >> 3;
    const int tok0 = tokg * 4;
    const int eL   = w*16 + esub*4;
    const int eG   = blockIdx.y*128;

    if (tid < 32){
        int idx = blockIdx.x*32 + tid;
        sga[tid] = g_flist[min(idx, cnt-1)];
    }
    __syncthreads();

    float qe[4][4], ke[4][4];
#pragma unroll
    for (int i=0;i<4;i++)
#pragma unroll
        for (int j=0;j<4;j++){ qe[i][j]=0.f; ke[i][j]=0.f; }

    for (int kc = 0; kc < DD; kc += 32){
        for (int v = tid; v < 1024; v += 256){
            int tk = v >> 5, k = v & 31;
            size_t g = (size_t)sga[tk];
            Xa[tk][k] = hid[g*DD + kc + k];
            Xb[tk][k] = hid[(g+1)*DD + kc + k];
        }
        for (int v = tid; v < 4096; v += 256){
            int e = v >> 5, k = v & 31;
            Wq[e][k] = wq[(size_t)(eG+e)*DD + kc + k];
            Wk[e][k] = wk[(size_t)(eG+e)*DD + kc + k];
        }
        __syncthreads();
#pragma unroll 4
        for (int k = 0; k < 32; ++k){
            float xa0 = Xa[tok0+0][k], xa1 = Xa[tok0+1][k], xa2 = Xa[tok0+2][k], xa3 = Xa[tok0+3][k];
            float xb0 = Xb[tok0+0][k], xb1 = Xb[tok0+1][k], xb2 = Xb[tok0+2][k], xb3 = Xb[tok0+3][k];
#pragma unroll
            for (int j = 0; j < 4; ++j){
                float wqv = Wq[eL+j][k], wkv = Wk[eL+j][k];
                qe[0][j] = fmaf(wqv, xa0, qe[0][j]);
                qe[1][j] = fmaf(wqv, xa1, qe[1][j]);
                qe[2][j] = fmaf(wqv, xa2, qe[2][j]);
                qe[3][j] = fmaf(wqv, xa3, qe[3][j]);
                ke[0][j] = fmaf(wkv, xb0, ke[0][j]);
                ke[1][j] = fmaf(wkv, xb1, ke[1][j]);
                ke[2][j] = fmaf(wkv, xb2, ke[2][j]);
                ke[3][j] = fmaf(wkv, xb3, ke[3][j]);
            }
        }
        __syncthreads();
    }

    float p[4];
#pragma unroll
    for (int i=0;i<4;i++){
        p[i] = 0.f;
#pragma unroll
        for (int j=0;j<4;j++) p[i] = fmaf(qe[i][j], ke[i][j], p[i]);
#pragma unroll
        for (int s = 8; s < 32; s <<= 1)
            p[i] += __shfl_xor_sync(0xffffffffu, p[i], s);
    }
    if (esub == 0){
#pragma unroll
        for (int i=0;i<4;i++) sred[w][tok0+i] = p[i];
    }
    __syncthreads();
    if (tid < 32){
        float s = 0.f;
#pragma unroll
        for (int ww=0; ww<8; ww++) s += sred[ww][tid];
        g_qkpart[(blockIdx.x*32 + tid)*8 + blockIdx.y] = s;
    }
}

__global__ __launch_bounds__(256)
void k_fix2()
{
    const int cnt = min(g_fcnt, FCAP);
    int i = blockIdx.x*256 + threadIdx.x;
    if (i >= cnt) return;
    float qk = 0.f;
#pragma unroll
    for (int y = 0; y < 8; ++y) qk += g_qkpart[i*8 + y];
    int g = g_flist[i];
    float cosv = qk * g_invnn[g];
    g_prob[g + 1] = fminf(fmaxf((1.f - cosv)*0.5f, 0.f), 1.f);
}

// ---------------- K2: mask scan / compaction ----------------
__global__ __launch_bounds__(1024)
void k_scan()
{
    const int b = blockIdx.x;
    const int tid = threadIdx.x;
    __shared__ int wsum[32];

    const int base = b*LL + tid*4;
    float p[4]; int m[4]; int s = 0;
#pragma unroll
    for (int i=0;i<4;i++){
        p[i] = g_prob[base+i];
        m[i] = p[i] > 0.5f ? 1 : 0;
        s += m[i];
    }
    const int lane = tid & 31, wid = tid >> 5;
    int incl = s;
#pragma unroll
    for (int o=1;o<32;o<<=1){
        int v = __shfl_up_sync(0xffffffffu, incl, o);
        if (lane >= o) incl += v;
    }
    if (lane == 31) wsum[wid] = incl;
    __syncthreads();
    if (tid < 32) {
        int v = wsum[tid];
        int iv = v;
#pragma unroll
        for (int o=1;o<32;o<<=1){
            int u = __shfl_up_sync(0xffffffffu, iv, o);
            if (tid >= o) iv += u;
        }
        wsum[tid] = iv - v;
    }
    __syncthreads();
    int run = incl - s + wsum[wid];
#pragma unroll
    for (int i=0;i<4;i++){
        if (m[i]) {
            g_src[b*LL + run]   = tid*4 + i;
            g_decay[b*LL + run] = fminf(fmaxf(1.f - p[i], 0.f), 1.f);
            run++;
        }
        g_cidx[base + i] = run - 1;
    }
    if (tid == 1023) g_counts[b] = run;
}

// ---------------- K3: EMA recurrence over chunks ----------------
__global__ __launch_bounds__(128)
void k_ema(const float* __restrict__ hid, const float* __restrict__ init)
{
    const int b = blockIdx.y;
    const int d = blockIdx.x * 128 + threadIdx.x;
    const float* hb = hid + (size_t)b*LL*DD;
    float state = init[b*DD + d];
    const int n = g_counts[b];
    const int*   src = g_src   + b*LL;
    const float* dec = g_decay + b*LL;
    float* emab = g_ema + (size_t)b*LL*DD;
    for (int j = 0; j < n; ++j) {
        int   t = __ldg(src + j);
        float a = __ldg(dec + j);
        float x = __ldg(hb + (size_t)t*DD + d);
        state = a*state + (1.f - a)*x;
        emab[(size_t)j*DD + d] = state;
    }
}

// ---------------- K4: broadcast back + residual ----------------
__global__ __launch_bounds__(256)
void k_out(const float* __restrict__ res, float* __restrict__ out)
{
    size_t gid  = (size_t)blockIdx.x * 256 + threadIdx.x;
    size_t flat = gid * 4;
    int d = (int)(flat & (DD-1));
    int t = (int)((flat >> 10) & (LL-1));
    int b = (int)(flat >> 22);
    int ci = g_cidx[b*LL + t];
    float4 r = *(const float4*)(res + flat);
    float4 e = *(const float4*)(g_ema + ((size_t)(b*LL + ci))*DD + d);
    float4 o = make_float4(r.x+e.x, r.y+e.y, r.z+e.z, r.w+e.w);
    *(float4*)(out + flat) = o;
}

// ---------------- launch ----------------
extern "C" void kernel_launch(void* const* d_in, const int* in_sizes, int n_in,
                              void* d_out, int out_size)
{
    const float* hid = (const float*)d_in[0];
    const float* res = (const float*)d_in[1];
    const float* wq  = (const float*)d_in[2];
    const float* wk  = (const float*)d_in[3];
    const float* ini = (const float*)d_in[4];
    float* out = (float*)d_out;

    float *xr, *wqr, *wkr;
    cudaGetSymbolAddress((void**)&xr,  g_xr);
    cudaGetSymbolAddress((void**)&wqr, g_wqr);
    cudaGetSymbolAddress((void**)&wkr, g_wkr);

    cudaFuncSetAttribute(k_rmma, cudaFuncAttributeMaxDynamicSharedMemorySize, RSMEM);

    const int nh4 = BB*LL*DD/4, nw4 = DD*DD/4;
    k_zero <<<1, 1>>>();
    k_round<<<(nh4+255)/256, 256>>>(hid, xr, nh4);
    k_round<<<(nw4+255)/256, 256>>>(wq, wqr, nw4);
    k_round<<<(nw4+255)/256, 256>>>(wk, wkr, nw4);

    k_rmma<<<dim3(32, BB), NT, RSMEM>>>();
    k_fix1<<<dim3(FCAP/32, 8), 256>>>(hid, wq, wk);
    k_fix2<<<(FCAP+255)/256, 256>>>();

    k_scan<<<BB, 1024>>>();
    k_ema <<<dim3(DD/128, BB), 128>>>(hid, ini);
    k_out <<<(BB*LL*DD/4 + 255)/256, 256>>>(res, out);
}

// round 15
// speedup vs baseline: 2.2577x; 1.1819x over previous
#include <cuda_runtime.h>
#include <cuda_bf16.h>
#include <cstdint>

#define BB 4
#define LL 4096
#define DD 1024
#define HT (BB*LL)
#define FCAP 8192
#define BANDC 1.5e-3f

// ---------------- scratch (static device globals; zero-initialized) ----------------
__device__ float g_prob[BB*LL];
__device__ float g_invnn[BB*LL];
__device__ float g_decay[BB*LL];
__device__ int   g_src[BB*LL];
__device__ int   g_cidx[BB*LL];
__device__ int   g_counts[BB];
__device__ int   g_fcnt;
__device__ int   g_flist[FCAP];
__device__ float g_qkpart[FCAP*8];
__device__ float g_ema[(size_t)BB*LL*DD];              // 64 MB
__device__ __nv_bfloat16 g_xb[(size_t)(HT+136)*DD];    // bf16 X; rows >= HT stay zero
__device__ __nv_bfloat16 g_wqb[(size_t)DD*DD];
__device__ __nv_bfloat16 g_wkb[(size_t)DD*DD];

// ---------------- helpers ----------------
__device__ __forceinline__ void cpa16s(uint32_t daddr, const void* src){
    asm volatile("cp.async.cg.shared.global [%0], [%1], 16;" :: "r"(daddr), "l"(src));
}
__device__ __forceinline__ void mma16(float* d, const uint32_t* a, const uint32_t* b){
    asm("mma.sync.aligned.m16n8k16.row.col.f32.bf16.bf16.f32 "
        "{%0,%1,%2,%3}, {%4,%5,%6,%7}, {%8,%9}, {%0,%1,%2,%3};"
        : "+f"(d[0]), "+f"(d[1]), "+f"(d[2]), "+f"(d[3])
        : "r"(a[0]), "r"(a[1]), "r"(a[2]), "r"(a[3]), "r"(b[0]), "r"(b[1]));
}
__device__ __forceinline__ void ldm4(uint32_t* r, uint32_t saddr){
    asm volatile("ldmatrix.sync.aligned.m8n8.x4.shared.b16 {%0,%1,%2,%3}, [%4];"
        : "=r"(r[0]), "=r"(r[1]), "=r"(r[2]), "=r"(r[3]) : "r"(saddr));
}

// ---------------- K0: convert fp32 -> bf16 ----------------
__global__ __launch_bounds__(256)
void k_cvt(const float* __restrict__ in, __nv_bfloat16* __restrict__ out, int n4)
{
    int i = blockIdx.x*256 + threadIdx.x;
    if (i >= n4) return;
    float4 x = ((const float4*)in)[i];
    __nv_bfloat162* o = (__nv_bfloat162*)(out + (size_t)i*4);
    o[0] = __floats2bfloat162_rn(x.x, x.y);
    o[1] = __floats2bfloat162_rn(x.z, x.w);
}
__global__ void k_zero(){ g_fcnt = 0; }

// ---------------- K1: bf16 HMMA router (512 thr, k-chunk=64, 3-stage) ----------------
// stage: A 129 rows (pad 132) x 64k bf16, row stride 144B ; B 256 rows x 64k, stride 144B
#define ASZ_B (132*144)                 // 19008 bytes
#define STG_B (ASZ_B + 256*144)         // 55872 bytes
#define RSMEM (3*STG_B)                 // 167616 bytes
#define NT 512

__device__ __forceinline__ void ld_stage(uint32_t sbb, size_t arow0, int e0, int kc, int tid)
{
    for (int v = tid; v < 3080; v += NT){
        const __nv_bfloat16* src;
        uint32_t dst;
        if (v < 1032){                       // A: 129 rows x 8 granules (16B = 8 bf16)
            int row = v >> 3, kg = v & 7;
            src = g_xb + (arow0 + (size_t)row)*DD + kc + kg*8;
            dst = (uint32_t)(row*144 + kg*16);
        } else {                             // B: 256 rows x 8 granules
            int u = v - 1032;
            int row = u >> 3, kg = u & 7;
            const __nv_bfloat16* w = (row < 128) ? g_wqb : g_wkb;
            src = w + (size_t)(e0 + (row & 127))*DD + kc + kg*8;
            dst = (uint32_t)(ASZ_B + row*144 + kg*16);
        }
        cpa16s(sbb + dst, src);
    }
}

extern __shared__ float dsm[];

__global__ __launch_bounds__(NT, 1)
void k_rmma()
{
    const int b   = blockIdx.y;
    const int t0  = blockIdx.x * 128;
    const int tid = threadIdx.x;
    const int wid = tid >> 5, lane = tid & 31;
    const int warp_m = wid & 3, warp_n = wid >> 2;   // 4 x 4 warp grid
    const int rm = warp_m*32, rn = warp_n*32;
    const int grp = lane >> 2, c = lane & 3;
    const size_t arow0 = (size_t)b*LL + t0;
    const uint32_t sbb = (uint32_t)__cvta_generic_to_shared(dsm);

    // ldmatrix per-lane source offsets (bytes, stage-relative)
    const int tile  = lane >> 3;         // 0..3
    const int rowin = lane & 7;
    // A m16k16 frag: tile0 rows r..r+7 k0-7 | tile1 r+8..r+15 k0-7 | tile2 r..r+7 k8-15 | tile3 r+8.. k8-15
    uint32_t offAq[2], offAk[2], offBq[2], offBk[2];
#pragma unroll
    for (int fm = 0; fm < 2; ++fm){
        int r = rm + fm*16 + rowin + (tile & 1)*8;
        offAq[fm] = (uint32_t)(r*144 + (tile >> 1)*16);
        offAk[fm] = offAq[fm] + 144;
    }
    // B n16k16 (2 fn per ldm4): tile0 e..e+7 k0-7 | tile1 e..e+7 k8-15 | tile2 e+8.. k0-7 | tile3 e+8.. k8-15
#pragma unroll
    for (int p = 0; p < 2; ++p){
        int e = rn + p*16 + (tile >> 1)*8 + rowin;
        offBq[p] = (uint32_t)(ASZ_B + e*144 + (tile & 1)*16);
        offBk[p] = offBq[p] + 128*144;
    }

    float qq[4], kk[4], qk[4];
#pragma unroll
    for (int i=0;i<4;i++){ qq[i]=0.f; kk[i]=0.f; qk[i]=0.f; }

    for (int ep = 0; ep < 8; ++ep){
        const int e0 = ep*128;
        float dq[2][4][4], dk[2][4][4];
#pragma unroll
        for (int fm=0; fm<2; fm++)
#pragma unroll
            for (int fn=0; fn<4; fn++)
#pragma unroll
                for (int r=0; r<4; r++){ dq[fm][fn][r]=0.f; dk[fm][fn][r]=0.f; }

        ld_stage(sbb,         arow0, e0,  0, tid);
        asm volatile("cp.async.commit_group;" ::: "memory");
        ld_stage(sbb + STG_B, arow0, e0, 64, tid);
        asm volatile("cp.async.commit_group;" ::: "memory");

        for (int ch = 0; ch < 16; ++ch){      // 16 chunks x 64 k
            if (ch < 15) asm volatile("cp.async.wait_group 1;" ::: "memory");
            else         asm volatile("cp.async.wait_group 0;" ::: "memory");
            __syncthreads();

            if (ch + 2 < 16){
                ld_stage(sbb + (uint32_t)(((ch+2)%3)*STG_B), arow0, e0, (ch+2)*64, tid);
                asm volatile("cp.async.commit_group;" ::: "memory");
            }

            const uint32_t sb = sbb + (uint32_t)((ch%3)*STG_B);

#pragma unroll
            for (int g = 0; g < 4; ++g){      // 4 x k16 per chunk
                const uint32_t kbB = (uint32_t)(g*32);  // 16 bf16 = 32 B
                uint32_t aq[2][4], ak[2][4], bq[2][4], bk[2][4];
                ldm4(aq[0], sb + offAq[0] + kbB);
                ldm4(aq[1], sb + offAq[1] + kbB);
                ldm4(ak[0], sb + offAk[0] + kbB);
                ldm4(ak[1], sb + offAk[1] + kbB);
                ldm4(bq[0], sb + offBq[0] + kbB);
                ldm4(bq[1], sb + offBq[1] + kbB);
                ldm4(bk[0], sb + offBk[0] + kbB);
                ldm4(bk[1], sb + offBk[1] + kbB);
#pragma unroll
                for (int fm = 0; fm < 2; ++fm)
#pragma unroll
                    for (int fn = 0; fn < 4; ++fn){
                        mma16(dq[fm][fn], aq[fm], &bq[fn>>1][(fn&1)*2]);
                        mma16(dk[fm][fn], ak[fm], &bk[fn>>1][(fn&1)*2]);
                    }
            }
        }
        __syncthreads();

        // fold this e-pass into per-row scalars (rows: rm + grp + fm*16 + h*8)
#pragma unroll
        for (int fm = 0; fm < 2; ++fm)
#pragma unroll
            for (int h = 0; h < 2; ++h){
                const int slot = fm*2 + h;
#pragma unroll
                for (int fn = 0; fn < 4; ++fn){
                    float q0 = dq[fm][fn][h*2], q1 = dq[fm][fn][h*2+1];
                    float k0 = dk[fm][fn][h*2], k1 = dk[fm][fn][h*2+1];
                    qq[slot] = fmaf(q0,q0, fmaf(q1,q1, qq[slot]));
                    kk[slot] = fmaf(k0,k0, fmaf(k1,k1, kk[slot]));
                    qk[slot] = fmaf(q0,k0, fmaf(q1,k1, qk[slot]));
                }
            }
    }

    // sum the 4 c-lanes of each quad (same rows, different output columns)
#pragma unroll
    for (int i = 0; i < 4; ++i){
#pragma unroll
        for (int s = 1; s < 4; s <<= 1){
            qq[i] += __shfl_xor_sync(0xffffffffu, qq[i], s);
            kk[i] += __shfl_xor_sync(0xffffffffu, kk[i], s);
            qk[i] += __shfl_xor_sync(0xffffffffu, qk[i], s);
        }
    }
    __syncthreads();
    float* red = dsm;   // 3 x 4 x 128 floats; pipeline fully drained
    if (c == 0){
#pragma unroll
        for (int slot = 0; slot < 4; ++slot){
            int row = rm + grp + (slot&1)*8 + (slot>>1)*16;
            red[       warp_n*128 + row] = qq[slot];
            red[512  + warp_n*128 + row] = kk[slot];
            red[1024 + warp_n*128 + row] = qk[slot];
        }
    }
    __syncthreads();
    if (tid < 128){
        float sqq = red[tid]      + red[128+tid]  + red[256+tid]  + red[384+tid];
        float skk = red[512+tid]  + red[640+tid]  + red[768+tid]  + red[896+tid];
        float sqk = red[1024+tid] + red[1152+tid] + red[1280+tid] + red[1408+tid];
        int t = t0 + tid;
        if (t < LL-1){
            float invnn = 1.f/(fmaxf(sqrtf(sqq),1e-12f)*fmaxf(sqrtf(skk),1e-12f));
            float cosv  = sqk * invnn;
            g_invnn[b*LL + t] = invnn;
            g_prob[b*LL + t + 1] = fminf(fmaxf((1.f - cosv)*0.5f, 0.f), 1.f);
            if (fabsf(cosv) < BANDC){
                int pos = atomicAdd(&g_fcnt, 1);
                if (pos < FCAP) g_flist[pos] = b*LL + t;
            }
        }
        if (t0 == 0 && tid == 0) g_prob[b*LL] = 1.0f;
    }
}

// ---------------- K1b: exact fp32 qk for flagged tokens ----------------
__global__ __launch_bounds__(256)
void k_fix1(const float* __restrict__ hid, const float* __restrict__ wq, const float* __restrict__ wk)
{
    __shared__ float Xa[32][33], Xb[32][33], Wq[128][33], Wk[128][33];
    __shared__ int   sga[32];
    __shared__ float sred[8][32];

    const int cnt = min(g_fcnt, FCAP);
    if ((int)blockIdx.x * 32 >= cnt) return;

    const int tid  = threadIdx.x;
    const int w    = tid >> 5, lane = tid & 31;
    const int tokg = lane & 7, esub = lane >> 3;
    const int tok0 = tokg * 4;
    const int eL   = w*16 + esub*4;
    const int eG   = blockIdx.y*128;

    if (tid < 32){
        int idx = blockIdx.x*32 + tid;
        sga[tid] = g_flist[min(idx, cnt-1)];
    }
    __syncthreads();

    float qe[4][4], ke[4][4];
#pragma unroll
    for (int i=0;i<4;i++)
#pragma unroll
        for (int j=0;j<4;j++){ qe[i][j]=0.f; ke[i][j]=0.f; }

    for (int kc = 0; kc < DD; kc += 32){
        for (int v = tid; v < 1024; v += 256){
            int tk = v >> 5, k = v & 31;
            size_t g = (size_t)sga[tk];
            Xa[tk][k] = hid[g*DD + kc + k];
            Xb[tk][k] = hid[(g+1)*DD + kc + k];
        }
        for (int v = tid; v < 4096; v += 256){
            int e = v >> 5, k = v & 31;
            Wq[e][k] = wq[(size_t)(eG+e)*DD + kc + k];
            Wk[e][k] = wk[(size_t)(eG+e)*DD + kc + k];
        }
        __syncthreads();
#pragma unroll 4
        for (int k = 0; k < 32; ++k){
            float xa0 = Xa[tok0+0][k], xa1 = Xa[tok0+1][k], xa2 = Xa[tok0+2][k], xa3 = Xa[tok0+3][k];
            float xb0 = Xb[tok0+0][k], xb1 = Xb[tok0+1][k], xb2 = Xb[tok0+2][k], xb3 = Xb[tok0+3][k];
#pragma unroll
            for (int j = 0; j < 4; ++j){
                float wqv = Wq[eL+j][k], wkv = Wk[eL+j][k];
                qe[0][j] = fmaf(wqv, xa0, qe[0][j]);
                qe[1][j] = fmaf(wqv, xa1, qe[1][j]);
                qe[2][j] = fmaf(wqv, xa2, qe[2][j]);
                qe[3][j] = fmaf(wqv, xa3, qe[3][j]);
                ke[0][j] = fmaf(wkv, xb0, ke[0][j]);
                ke[1][j] = fmaf(wkv, xb1, ke[1][j]);
                ke[2][j] = fmaf(wkv, xb2, ke[2][j]);
                ke[3][j] = fmaf(wkv, xb3, ke[3][j]);
            }
        }
        __syncthreads();
    }

    float p[4];
#pragma unroll
    for (int i=0;i<4;i++){
        p[i] = 0.f;
#pragma unroll
        for (int j=0;j<4;j++) p[i] = fmaf(qe[i][j], ke[i][j], p[i]);
#pragma unroll
        for (int s = 8; s < 32; s <<= 1)
            p[i] += __shfl_xor_sync(0xffffffffu, p[i], s);
    }
    if (esub == 0){
#pragma unroll
        for (int i=0;i<4;i++) sred[w][tok0+i] = p[i];
    }
    __syncthreads();
    if (tid < 32){
        float s = 0.f;
#pragma unroll
        for (int ww=0; ww<8; ww++) s += sred[ww][tid];
        g_qkpart[(blockIdx.x*32 + tid)*8 + blockIdx.y] = s;
    }
}

__global__ __launch_bounds__(256)
void k_fix2()
{
    const int cnt = min(g_fcnt, FCAP);
    int i = blockIdx.x*256 + threadIdx.x;
    if (i >= cnt) return;
    float qk = 0.f;
#pragma unroll
    for (int y = 0; y < 8; ++y) qk += g_qkpart[i*8 + y];
    int g = g_flist[i];
    float cosv = qk * g_invnn[g];
    g_prob[g + 1] = fminf(fmaxf((1.f - cosv)*0.5f, 0.f), 1.f);
}

// ---------------- K2: mask scan / compaction ----------------
__global__ __launch_bounds__(1024)
void k_scan()
{
    const int b = blockIdx.x;
    const int tid = threadIdx.x;
    __shared__ int wsum[32];

    const int base = b*LL + tid*4;
    float p[4]; int m[4]; int s = 0;
#pragma unroll
    for (int i=0;i<4;i++){
        p[i] = g_prob[base+i];
        m[i] = p[i] > 0.5f ? 1 : 0;
        s += m[i];
    }
    const int lane = tid & 31, wid = tid >> 5;
    int incl = s;
#pragma unroll
    for (int o=1;o<32;o<<=1){
        int v = __shfl_up_sync(0xffffffffu, incl, o);
        if (lane >= o) incl += v;
    }
    if (lane == 31) wsum[wid] = incl;
    __syncthreads();
    if (tid < 32) {
        int v = wsum[tid];
        int iv = v;
#pragma unroll
        for (int o=1;o<32;o<<=1){
            int u = __shfl_up_sync(0xffffffffu, iv, o);
            if (tid >= o) iv += u;
        }
        wsum[tid] = iv - v;
    }
    __syncthreads();
    int run = incl - s + wsum[wid];
#pragma unroll
    for (int i=0;i<4;i++){
        if (m[i]) {
            g_src[b*LL + run]   = tid*4 + i;
            g_decay[b*LL + run] = fminf(fmaxf(1.f - p[i], 0.f), 1.f);
            run++;
        }
        g_cidx[base + i] = run - 1;
    }
    if (tid == 1023) g_counts[b] = run;
}

// ---------------- K3: EMA recurrence over chunks ----------------
__global__ __launch_bounds__(128)
void k_ema(const float* __restrict__ hid, const float* __restrict__ init)
{
    const int b = blockIdx.y;
    const int d = blockIdx.x * 128 + threadIdx.x;
    const float* hb = hid + (size_t)b*LL*DD;
    float state = init[b*DD + d];
    const int n = g_counts[b];
    const int*   src = g_src   + b*LL;
    const float* dec = g_decay + b*LL;
    float* emab = g_ema + (size_t)b*LL*DD;
    for (int j = 0; j < n; ++j) {
        int   t = __ldg(src + j);
        float a = __ldg(dec + j);
        float x = __ldg(hb + (size_t)t*DD + d);
        state = a*state + (1.f - a)*x;
        emab[(size_t)j*DD + d] = state;
    }
}

// ---------------- K4: broadcast back + residual ----------------
__global__ __launch_bounds__(256)
void k_out(const float* __restrict__ res, float* __restrict__ out)
{
    size_t gid  = (size_t)blockIdx.x * 256 + threadIdx.x;
    size_t flat = gid * 4;
    int d = (int)(flat & (DD-1));
    int t = (int)((flat >> 10) & (LL-1));
    int b = (int)(flat >> 22);
    int ci = g_cidx[b*LL + t];
    float4 r = *(const float4*)(res + flat);
    float4 e = *(const float4*)(g_ema + ((size_t)(b*LL + ci))*DD + d);
    float4 o = make_float4(r.x+e.x, r.y+e.y, r.z+e.z, r.w+e.w);
    *(float4*)(out + flat) = o;
}

// ---------------- launch ----------------
extern "C" void kernel_launch(void* const* d_in, const int* in_sizes, int n_in,
                              void* d_out, int out_size)
{
    const float* hid = (const float*)d_in[0];
    const float* res = (const float*)d_in[1];
    const float* wq  = (const float*)d_in[2];
    const float* wk  = (const float*)d_in[3];
    const float* ini = (const float*)d_in[4];
    float* out = (float*)d_out;

    __nv_bfloat16 *xb, *wqb, *wkb;
    cudaGetSymbolAddress((void**)&xb,  g_xb);
    cudaGetSymbolAddress((void**)&wqb, g_wqb);
    cudaGetSymbolAddress((void**)&wkb, g_wkb);

    cudaFuncSetAttribute(k_rmma, cudaFuncAttributeMaxDynamicSharedMemorySize, RSMEM);

    const int nh4 = BB*LL*DD/4, nw4 = DD*DD/4;
    k_zero<<<1, 1>>>();
    k_cvt <<<(nh4+255)/256, 256>>>(hid, xb, nh4);
    k_cvt <<<(nw4+255)/256, 256>>>(wq, wqb, nw4);
    k_cvt <<<(nw4+255)/256, 256>>>(wk, wkb, nw4);

    k_rmma<<<dim3(32, BB), NT, RSMEM>>>();
    k_fix1<<<dim3(FCAP/32, 8), 256>>>(hid, wq, wk);
    k_fix2<<<(FCAP+255)/256, 256>>>();

    k_scan<<<BB, 1024>>>();
    k_ema <<<dim3(DD/128, BB), 128>>>(hid, ini);
    k_out <<<(BB*LL*DD/4 + 255)/256, 256>>>(res, out);
}

// round 17
// speedup vs baseline: 3.0274x; 1.3410x over previous
#include <cuda_runtime.h>
#include <cuda_bf16.h>
#include <cstdint>

#define BB 4
#define LL 4096
#define DD 1024
#define HT (BB*LL)
#define FCAP 8192
#define BANDC 1.5e-3f

// ---------------- scratch (static device globals; zero-initialized) ----------------
__device__ float g_prob[BB*LL];
__device__ float g_invnn[BB*LL];
__device__ float g_decay[BB*LL];
__device__ int   g_src[BB*LL];
__device__ int   g_cidx[BB*LL];
__device__ int   g_counts[BB];
__device__ int   g_fcnt;
__device__ int   g_flist[FCAP];
__device__ float g_qkpart[FCAP*8];
__device__ float g_ema[(size_t)BB*LL*DD];              // 64 MB
__device__ __nv_bfloat16 g_xb[(size_t)(HT+136)*DD];    // bf16 X; rows >= HT stay zero
__device__ __nv_bfloat16 g_wqb[(size_t)DD*DD];
__device__ __nv_bfloat16 g_wkb[(size_t)DD*DD];

// ---------------- helpers ----------------
__device__ __forceinline__ void cpa16s(uint32_t daddr, const void* src){
    asm volatile("cp.async.cg.shared.global [%0], [%1], 16;" :: "r"(daddr), "l"(src));
}
__device__ __forceinline__ void mma16(float* d, const uint32_t* a, const uint32_t* b){
    asm("mma.sync.aligned.m16n8k16.row.col.f32.bf16.bf16.f32 "
        "{%0,%1,%2,%3}, {%4,%5,%6,%7}, {%8,%9}, {%0,%1,%2,%3};"
        : "+f"(d[0]), "+f"(d[1]), "+f"(d[2]), "+f"(d[3])
        : "r"(a[0]), "r"(a[1]), "r"(a[2]), "r"(a[3]), "r"(b[0]), "r"(b[1]));
}
__device__ __forceinline__ void ldm4(uint32_t* r, uint32_t saddr){
    asm volatile("ldmatrix.sync.aligned.m8n8.x4.shared.b16 {%0,%1,%2,%3}, [%4];"
        : "=r"(r[0]), "=r"(r[1]), "=r"(r[2]), "=r"(r[3]) : "r"(saddr));
}

// ---------------- K0: convert fp32 -> bf16 ----------------
__global__ __launch_bounds__(256)
void k_cvt(const float* __restrict__ in, __nv_bfloat16* __restrict__ out, int n4)
{
    int i = blockIdx.x*256 + threadIdx.x;
    if (i >= n4) return;
    float4 x = ((const float4*)in)[i];
    __nv_bfloat162* o = (__nv_bfloat162*)(out + (size_t)i*4);
    o[0] = __floats2bfloat162_rn(x.x, x.y);
    o[1] = __floats2bfloat162_rn(x.z, x.w);
}
__global__ void k_zero(){ g_fcnt = 0; }

// ---------------- K1: bf16 HMMA router (512 thr, k-chunk=64, 3-stage) ----------------
// stage: A 129 rows (pad 132) x 64k bf16, row stride 144B ; B 256 rows x 64k, stride 144B
#define ASZ_B (132*144)                 // 19008 bytes
#define STG_B (ASZ_B + 256*144)         // 55872 bytes
#define RSMEM (3*STG_B)                 // 167616 bytes
#define NT 512

__device__ __forceinline__ void ld_stage(uint32_t sbb, size_t arow0, int e0, int kc, int tid)
{
    for (int v = tid; v < 3080; v += NT){
        const __nv_bfloat16* src;
        uint32_t dst;
        if (v < 1032){                       // A: 129 rows x 8 granules (16B = 8 bf16)
            int row = v >> 3, kg = v & 7;
            src = g_xb + (arow0 + (size_t)row)*DD + kc + kg*8;
            dst = (uint32_t)(row*144 + kg*16);
        } else {                             // B: 256 rows x 8 granules
            int u = v - 1032;
            int row = u >> 3, kg = u & 7;
            const __nv_bfloat16* w = (row < 128) ? g_wqb : g_wkb;
            src = w + (size_t)(e0 + (row & 127))*DD + kc + kg*8;
            dst = (uint32_t)(ASZ_B + row*144 + kg*16);
        }
        cpa16s(sbb + dst, src);
    }
}

extern __shared__ float dsm[];

__global__ __launch_bounds__(NT, 1)
void k_rmma()
{
    const int b   = blockIdx.y;
    const int t0  = blockIdx.x * 128;
    const int tid = threadIdx.x;
    const int wid = tid >> 5, lane = tid & 31;
    const int warp_m = wid & 3, warp_n = wid >> 2;   // 4 x 4 warp grid
    const int rm = warp_m*32, rn = warp_n*32;
    const int grp = lane >> 2, c = lane & 3;
    const size_t arow0 = (size_t)b*LL + t0;
    const uint32_t sbb = (uint32_t)__cvta_generic_to_shared(dsm);

    // ldmatrix per-lane source offsets (bytes, stage-relative)
    const int tile  = lane >> 3;         // 0..3
    const int rowin = lane & 7;
    uint32_t offAq[2], offAk[2], offBq[2], offBk[2];
#pragma unroll
    for (int fm = 0; fm < 2; ++fm){
        int r = rm + fm*16 + rowin + (tile & 1)*8;
        offAq[fm] = (uint32_t)(r*144 + (tile >> 1)*16);
        offAk[fm] = offAq[fm] + 144;
    }
#pragma unroll
    for (int p = 0; p < 2; ++p){
        int e = rn + p*16 + (tile >> 1)*8 + rowin;
        offBq[p] = (uint32_t)(ASZ_B + e*144 + (tile & 1)*16);
        offBk[p] = offBq[p] + 128*144;
    }

    float qq[4], kk[4], qk[4];
#pragma unroll
    for (int i=0;i<4;i++){ qq[i]=0.f; kk[i]=0.f; qk[i]=0.f; }

    for (int ep = 0; ep < 8; ++ep){
        const int e0 = ep*128;
        float dq[2][4][4], dk[2][4][4];
#pragma unroll
        for (int fm=0; fm<2; fm++)
#pragma unroll
            for (int fn=0; fn<4; fn++)
#pragma unroll
                for (int r=0; r<4; r++){ dq[fm][fn][r]=0.f; dk[fm][fn][r]=0.f; }

        ld_stage(sbb,         arow0, e0,  0, tid);
        asm volatile("cp.async.commit_group;" ::: "memory");
        ld_stage(sbb + STG_B, arow0, e0, 64, tid);
        asm volatile("cp.async.commit_group;" ::: "memory");

        for (int ch = 0; ch < 16; ++ch){      // 16 chunks x 64 k
            if (ch < 15) asm volatile("cp.async.wait_group 1;" ::: "memory");
            else         asm volatile("cp.async.wait_group 0;" ::: "memory");
            __syncthreads();

            if (ch + 2 < 16){
                ld_stage(sbb + (uint32_t)(((ch+2)%3)*STG_B), arow0, e0, (ch+2)*64, tid);
                asm volatile("cp.async.commit_group;" ::: "memory");
            }

            const uint32_t sb = sbb + (uint32_t)((ch%3)*STG_B);

#pragma unroll
            for (int g = 0; g < 4; ++g){      // 4 x k16 per chunk
                const uint32_t kbB = (uint32_t)(g*32);  // 16 bf16 = 32 B
                uint32_t aq[2][4], ak[2][4], bq[2][4], bk[2][4];
                ldm4(aq[0], sb + offAq[0] + kbB);
                ldm4(aq[1], sb + offAq[1] + kbB);
                ldm4(ak[0], sb + offAk[0] + kbB);
                ldm4(ak[1], sb + offAk[1] + kbB);
                ldm4(bq[0], sb + offBq[0] + kbB);
                ldm4(bq[1], sb + offBq[1] + kbB);
                ldm4(bk[0], sb + offBk[0] + kbB);
                ldm4(bk[1], sb + offBk[1] + kbB);
#pragma unroll
                for (int fm = 0; fm < 2; ++fm)
#pragma unroll
                    for (int fn = 0; fn < 4; ++fn){
                        mma16(dq[fm][fn], aq[fm], &bq[fn>>1][(fn&1)*2]);
                        mma16(dk[fm][fn], ak[fm], &bk[fn>>1][(fn&1)*2]);
                    }
            }
        }
        __syncthreads();

        // fold this e-pass into per-row scalars (rows: rm + grp + fm*16 + h*8)
#pragma unroll
        for (int fm = 0; fm < 2; ++fm)
#pragma unroll
            for (int h = 0; h < 2; ++h){
                const int slot = fm*2 + h;
#pragma unroll
                for (int fn = 0; fn < 4; ++fn){
                    float q0 = dq[fm][fn][h*2], q1 = dq[fm][fn][h*2+1];
                    float k0 = dk[fm][fn][h*2], k1 = dk[fm][fn][h*2+1];
                    qq[slot] = fmaf(q0,q0, fmaf(q1,q1, qq[slot]));
                    kk[slot] = fmaf(k0,k0, fmaf(k1,k1, kk[slot]));
                    qk[slot] = fmaf(q0,k0, fmaf(q1,k1, qk[slot]));
                }
            }
    }

    // sum the 4 c-lanes of each quad (same rows, different output columns)
#pragma unroll
    for (int i = 0; i < 4; ++i){
#pragma unroll
        for (int s = 1; s < 4; s <<= 1){
            qq[i] += __shfl_xor_sync(0xffffffffu, qq[i], s);
            kk[i] += __shfl_xor_sync(0xffffffffu, kk[i], s);
            qk[i] += __shfl_xor_sync(0xffffffffu, qk[i], s);
        }
    }
    __syncthreads();
    float* red = dsm;   // 3 x 4 x 128 floats; pipeline fully drained
    if (c == 0){
#pragma unroll
        for (int slot = 0; slot < 4; ++slot){
            int row = rm + grp + (slot&1)*8 + (slot>>1)*16;
            red[       warp_n*128 + row] = qq[slot];
            red[512  + warp_n*128 + row] = kk[slot];
            red[1024 + warp_n*128 + row] = qk[slot];
        }
    }
    __syncthreads();
    if (tid < 128){
        float sqq = red[tid]      + red[128+tid]  + red[256+tid]  + red[384+tid];
        float skk = red[512+tid]  + red[640+tid]  + red[768+tid]  + red[896+tid];
        float sqk = red[1024+tid] + red[1152+tid] + red[1280+tid] + red[1408+tid];
        int t = t0 + tid;
        if (t < LL-1){
            float invnn = 1.f/(fmaxf(sqrtf(sqq),1e-12f)*fmaxf(sqrtf(skk),1e-12f));
            float cosv  = sqk * invnn;
            g_invnn[b*LL + t] = invnn;
            g_prob[b*LL + t + 1] = fminf(fmaxf((1.f - cosv)*0.5f, 0.f), 1.f);
            if (fabsf(cosv) < BANDC){
                int pos = atomicAdd(&g_fcnt, 1);
                if (pos < FCAP) g_flist[pos] = b*LL + t;
            }
        }
        if (t0 == 0 && tid == 0) g_prob[b*LL] = 1.0f;
    }
}

// ---------------- K1b: exact fp32 qk for flagged tokens ----------------
__global__ __launch_bounds__(256)
void k_fix1(const float* __restrict__ hid, const float* __restrict__ wq, const float* __restrict__ wk)
{
    __shared__ float Xa[32][33], Xb[32][33], Wq[128][33], Wk[128][33];
    __shared__ int   sga[32];
    __shared__ float sred[8][32];

    const int cnt = min(g_fcnt, FCAP);
    if ((int)blockIdx.x * 32 >= cnt) return;

    const int tid  = threadIdx.x;
    const int w    = tid >> 5, lane = tid & 31;
    const int tokg = lane & 7, esub = lane >> 3;
    const int tok0 = tokg * 4;
    const int eL   = w*16 + esub*4;
    const int eG   = blockIdx.y*128;

    if (tid < 32){
        int idx = blockIdx.x*32 + tid;
        sga[tid] = g_flist[min(idx, cnt-1)];
    }
    __syncthreads();

    float qe[4][4], ke[4][4];
#pragma unroll
    for (int i=0;i<4;i++)
#pragma unroll
        for (int j=0;j<4;j++){ qe[i][j]=0.f; ke[i][j]=0.f; }

    for (int kc = 0; kc < DD; kc += 32){
        for (int v = tid; v < 1024; v += 256){
            int tk = v >> 5, k = v & 31;
            size_t g = (size_t)sga[tk];
            Xa[tk][k] = hid[g*DD + kc + k];
            Xb[tk][k] = hid[(g+1)*DD + kc + k];
        }
        for (int v = tid; v < 4096; v += 256){
            int e = v >> 5, k = v & 31;
            Wq[e][k] = wq[(size_t)(eG+e)*DD + kc + k];
            Wk[e][k] = wk[(size_t)(eG+e)*DD + kc + k];
        }
        __syncthreads();
#pragma unroll 4
        for (int k = 0; k < 32; ++k){
            float xa0 = Xa[tok0+0][k], xa1 = Xa[tok0+1][k], xa2 = Xa[tok0+2][k], xa3 = Xa[tok0+3][k];
            float xb0 = Xb[tok0+0][k], xb1 = Xb[tok0+1][k], xb2 = Xb[tok0+2][k], xb3 = Xb[tok0+3][k];
#pragma unroll
            for (int j = 0; j < 4; ++j){
                float wqv = Wq[eL+j][k], wkv = Wk[eL+j][k];
                qe[0][j] = fmaf(wqv, xa0, qe[0][j]);
                qe[1][j] = fmaf(wqv, xa1, qe[1][j]);
                qe[2][j] = fmaf(wqv, xa2, qe[2][j]);
                qe[3][j] = fmaf(wqv, xa3, qe[3][j]);
                ke[0][j] = fmaf(wkv, xb0, ke[0][j]);
                ke[1][j] = fmaf(wkv, xb1, ke[1][j]);
                ke[2][j] = fmaf(wkv, xb2, ke[2][j]);
                ke[3][j] = fmaf(wkv, xb3, ke[3][j]);
            }
        }
        __syncthreads();
    }

    float p[4];
#pragma unroll
    for (int i=0;i<4;i++){
        p[i] = 0.f;
#pragma unroll
        for (int j=0;j<4;j++) p[i] = fmaf(qe[i][j], ke[i][j], p[i]);
#pragma unroll
        for (int s = 8; s < 32; s <<= 1)
            p[i] += __shfl_xor_sync(0xffffffffu, p[i], s);
    }
    if (esub == 0){
#pragma unroll
        for (int i=0;i<4;i++) sred[w][tok0+i] = p[i];
    }
    __syncthreads();
    if (tid < 32){
        float s = 0.f;
#pragma unroll
        for (int ww=0; ww<8; ww++) s += sred[ww][tid];
        g_qkpart[(blockIdx.x*32 + tid)*8 + blockIdx.y] = s;
    }
}

__global__ __launch_bounds__(256)
void k_fix2()
{
    const int cnt = min(g_fcnt, FCAP);
    int i = blockIdx.x*256 + threadIdx.x;
    if (i >= cnt) return;
    float qk = 0.f;
#pragma unroll
    for (int y = 0; y < 8; ++y) qk += g_qkpart[i*8 + y];
    int g = g_flist[i];
    float cosv = qk * g_invnn[g];
    g_prob[g + 1] = fminf(fmaxf((1.f - cosv)*0.5f, 0.f), 1.f);
}

// ---------------- K2: mask scan / compaction ----------------
__global__ __launch_bounds__(1024)
void k_scan()
{
    const int b = blockIdx.x;
    const int tid = threadIdx.x;
    __shared__ int wsum[32];

    const int base = b*LL + tid*4;
    float p[4]; int m[4]; int s = 0;
#pragma unroll
    for (int i=0;i<4;i++){
        p[i] = g_prob[base+i];
        m[i] = p[i] > 0.5f ? 1 : 0;
        s += m[i];
    }
    const int lane = tid & 31, wid = tid >> 5;
    int incl = s;
#pragma unroll
    for (int o=1;o<32;o<<=1){
        int v = __shfl_up_sync(0xffffffffu, incl, o);
        if (lane >= o) incl += v;
    }
    if (lane == 31) wsum[wid] = incl;
    __syncthreads();
    if (tid < 32) {
        int v = wsum[tid];
        int iv = v;
#pragma unroll
        for (int o=1;o<32;o<<=1){
            int u = __shfl_up_sync(0xffffffffu, iv, o);
            if (tid >= o) iv += u;
        }
        wsum[tid] = iv - v;
    }
    __syncthreads();
    int run = incl - s + wsum[wid];
#pragma unroll
    for (int i=0;i<4;i++){
        if (m[i]) {
            g_src[b*LL + run]   = tid*4 + i;
            g_decay[b*LL + run] = fminf(fmaxf(1.f - p[i], 0.f), 1.f);
            run++;
        }
        g_cidx[base + i] = run - 1;
    }
    if (tid == 1023) g_counts[b] = run;
}

// ---------------- K3: EMA recurrence, PF=16 software-pipelined prefetch ----------------
#define PF 16
__global__ __launch_bounds__(128)
void k_ema(const float* __restrict__ hid, const float* __restrict__ init)
{
    const int b = blockIdx.y;
    const int d = blockIdx.x * 128 + threadIdx.x;
    const float* hb = hid + (size_t)b*LL*DD;
    float state = init[b*DD + d];
    const int n = g_counts[b];
    const int*   src = g_src   + b*LL;
    const float* dec = g_decay + b*LL;
    float* emab = g_ema + (size_t)b*LL*DD;

    float xbuf[PF], abuf[PF];
#pragma unroll
    for (int s = 0; s < PF; ++s){
        if (s < n){
            int t = __ldg(src + s);
            abuf[s] = __ldg(dec + s);
            xbuf[s] = __ldg(hb + (size_t)t*DD + d);
        } else { abuf[s] = 0.f; xbuf[s] = 0.f; }
    }

    int j = 0;
    for (; j + PF <= n; j += PF){
#pragma unroll
        for (int s = 0; s < PF; ++s){
            float a = abuf[s], x = xbuf[s];
            int jn = j + s + PF;
            if (jn < n){
                int t = __ldg(src + jn);
                abuf[s] = __ldg(dec + jn);
                xbuf[s] = __ldg(hb + (size_t)t*DD + d);
            }
            state = a*state + (1.f - a)*x;
            emab[(size_t)(j + s)*DD + d] = state;
        }
    }
    // remainder: slots 0..(n-j-1) hold entries j..n-1
#pragma unroll
    for (int s = 0; s < PF; ++s){
        if (j + s < n){
            float a = abuf[s], x = xbuf[s];
            state = a*state + (1.f - a)*x;
            emab[(size_t)(j + s)*DD + d] = state;
        }
    }
}

// ---------------- K4: broadcast back + residual ----------------
__global__ __launch_bounds__(256)
void k_out(const float* __restrict__ res, float* __restrict__ out)
{
    size_t gid  = (size_t)blockIdx.x * 256 + threadIdx.x;
    size_t flat = gid * 4;
    int d = (int)(flat & (DD-1));
    int t = (int)((flat >> 10) & (LL-1));
    int b = (int)(flat >> 22);
    int ci = g_cidx[b*LL + t];
    float4 r = *(const float4*)(res + flat);
    float4 e = *(const float4*)(g_ema + ((size_t)(b*LL + ci))*DD + d);
    float4 o = make_float4(r.x+e.x, r.y+e.y, r.z+e.z, r.w+e.w);
    *(float4*)(out + flat) = o;
}

// ---------------- launch ----------------
extern "C" void kernel_launch(void* const* d_in, const int* in_sizes, int n_in,
                              void* d_out, int out_size)
{
    const float* hid = (const float*)d_in[0];
    const float* res = (const float*)d_in[1];
    const float* wq  = (const float*)d_in[2];
    const float* wk  = (const float*)d_in[3];
    const float* ini = (const float*)d_in[4];
    float* out = (float*)d_out;

    __nv_bfloat16 *xb, *wqb, *wkb;
    cudaGetSymbolAddress((void**)&xb,  g_xb);
    cudaGetSymbolAddress((void**)&wqb, g_wqb);
    cudaGetSymbolAddress((void**)&wkb, g_wkb);

    cudaFuncSetAttribute(k_rmma, cudaFuncAttributeMaxDynamicSharedMemorySize, RSMEM);

    const int nh4 = BB*LL*DD/4, nw4 = DD*DD/4;
    k_zero<<<1, 1>>>();
    k_cvt <<<(nh4+255)/256, 256>>>(hid, xb, nh4);
    k_cvt <<<(nw4+255)/256, 256>>>(wq, wqb, nw4);
    k_cvt <<<(nw4+255)/256, 256>>>(wk, wkb, nw4);

    k_rmma<<<dim3(32, BB), NT, RSMEM>>>();
    k_fix1<<<dim3(FCAP/32, 8), 256>>>(hid, wq, wk);
    k_fix2<<<(FCAP+255)/256, 256>>>();

    k_scan<<<BB, 1024>>>();
    k_ema <<<dim3(DD/128, BB), 128>>>(hid, ini);
    k_out <<<(BB*LL*DD/4 + 255)/256, 256>>>(res, out);
}